// round 1
// baseline (speedup 1.0000x reference)
#include <cuda_runtime.h>
#include <cuda_bf16.h>
#include <cstdint>

// ---------------- problem constants ----------------
#define NN 50000      // nodes
#define FI 112        // feature dim layer1
#define DM 32         // dim layer2
#define NG 256        // graphs
#define BN_EPS 1e-5f

// ---------------- device scratch (no allocs allowed) ----------------
__device__ float  g_A [NN * FI];   // x + agg1, input to MLP1
__device__ float  g_T [NN * FI];   // MLP intermediate
__device__ float  g_H [NN * FI];   // MLP1 out / bn1 normalized (in place)
__device__ float  g_B [NN * FI];   // hn + agg2
__device__ float  g_T2[NN * DM];
__device__ float  g_H2[NN * DM];
__device__ double g_sum1[FI], g_sq1[FI];
__device__ double g_sum2[DM], g_sq2[DM];
__device__ float  g_pool[NG * DM];

// ---------------- small utility kernels ----------------
__global__ void zero_scratch_kernel() {
    int t = blockIdx.x * blockDim.x + threadIdx.x;
    if (t < FI) { g_sum1[t] = 0.0; g_sq1[t] = 0.0; }
    if (t < DM) { g_sum2[t] = 0.0; g_sq2[t] = 0.0; }
    if (t < NG * DM) g_pool[t] = 0.0f;
}

__global__ void copy4_kernel(float4* __restrict__ dst, const float4* __restrict__ src, int n4) {
    int i = blockIdx.x * blockDim.x + threadIdx.x;
    if (i < n4) dst[i] = src[i];
}

// ---------------- edge scatter: Acc[dst] += X[src], F=112 (28 float4 chunks) ----------------
__global__ void scatter_add112_kernel(const float* __restrict__ X,
                                      const int* __restrict__ src,
                                      const int* __restrict__ dst,
                                      float* __restrict__ Acc, int E) {
    int idx = blockIdx.x * blockDim.x + threadIdx.x;
    int total = E * 28;
    if (idx >= total) return;
    int e = idx / 28;
    int c = idx % 28;
    int s = __ldg(&src[e]);
    int d = __ldg(&dst[e]);
    const float4 v = *reinterpret_cast<const float4*>(X + (size_t)s * FI + c * 4);
    float* p = Acc + (size_t)d * FI + c * 4;
    atomicAdd(p + 0, v.x);
    atomicAdd(p + 1, v.y);
    atomicAdd(p + 2, v.z);
    atomicAdd(p + 3, v.w);
}

// ---------------- GEMM: C = relu(A[M,K] @ W[K,N] + b), blockDim = N ----------------
template<int K, int N, int ROWS>
__global__ void gemm_bias_relu_kernel(const float* __restrict__ A,
                                      const float* __restrict__ W,
                                      const float* __restrict__ bias,
                                      float* __restrict__ C, int M) {
    __shared__ float As[ROWS][K];
    const int f    = threadIdx.x;            // 0..N-1
    const int row0 = blockIdx.x * ROWS;

    for (int i = f; i < ROWS * K; i += N) {
        int r = i / K, k = i % K;
        As[r][k] = (row0 + r < M) ? A[(size_t)(row0 + r) * K + k] : 0.0f;
    }
    __syncthreads();

    float acc[ROWS];
#pragma unroll
    for (int r = 0; r < ROWS; r++) acc[r] = 0.0f;

#pragma unroll 4
    for (int k = 0; k < K; k++) {
        float w = __ldg(&W[k * N + f]);
#pragma unroll
        for (int r = 0; r < ROWS; r++) acc[r] += As[r][k] * w;
    }

    float bb = __ldg(&bias[f]);
#pragma unroll
    for (int r = 0; r < ROWS; r++) {
        if (row0 + r < M)
            C[(size_t)(row0 + r) * N + f] = fmaxf(acc[r] + bb, 0.0f);
    }
}

// ---------------- BatchNorm stats (double accumulation) ----------------
template<int N>
__global__ void bn_stats_kernel(const float* __restrict__ H, int M,
                                double* __restrict__ sum, double* __restrict__ sq) {
    int f = threadIdx.x;  // blockDim = N
    double s = 0.0, s2 = 0.0;
    for (int i = blockIdx.x; i < M; i += gridDim.x) {
        double v = (double)H[(size_t)i * N + f];
        s  += v;
        s2 += v * v;
    }
    atomicAdd(&sum[f], s);
    atomicAdd(&sq[f],  s2);
}

// ---------------- BatchNorm normalize in place ----------------
template<int N>
__global__ void bn_norm_kernel(float* __restrict__ H, int M,
                               const double* __restrict__ sum, const double* __restrict__ sq,
                               const float* __restrict__ gamma, const float* __restrict__ beta) {
    int idx = blockIdx.x * blockDim.x + threadIdx.x;
    if (idx >= M * N) return;
    int f = idx % N;
    double m   = sum[f] / (double)M;
    double var = sq[f] / (double)M - m * m;
    float  rs  = rsqrtf((float)var + BN_EPS);
    float  v   = H[idx];
    H[idx] = ((v - (float)m) * rs) * __ldg(&gamma[f]) + __ldg(&beta[f]);
}

// ---------------- global add pool ----------------
__global__ void pool_kernel(const float* __restrict__ H2, const int* __restrict__ batch, int M) {
    int idx = blockIdx.x * blockDim.x + threadIdx.x;
    if (idx >= M * DM) return;
    int i = idx / DM;
    int f = idx % DM;
    atomicAdd(&g_pool[__ldg(&batch[i]) * DM + f], H2[idx]);
}

// ---------------- dense head: 256 graphs, one block each ----------------
__global__ void head_kernel(const float* __restrict__ fcxd_w, const float* __restrict__ fcxd_b,
                            const float* __restrict__ fc1_w,  const float* __restrict__ fc1_b,
                            const float* __restrict__ fc2_w,  const float* __restrict__ fc2_b,
                            const float* __restrict__ fc3_w,  const float* __restrict__ fc3_b,
                            const float* __restrict__ fc4_w,  const float* __restrict__ fc4_b,
                            const float* __restrict__ fc5_w,  const float* __restrict__ fc5_b,
                            float* __restrict__ out) {
    __shared__ float p[DM], z1[64], z2[32], z3[16], z4[8], z5[2];
    int g = blockIdx.x, t = threadIdx.x;
    if (t < DM) p[t] = g_pool[g * DM + t];
    __syncthreads();
    if (t < 64) {
        float s = fcxd_b[t];
        for (int k = 0; k < 32; k++) s += p[k] * fcxd_w[k * 64 + t];
        z1[t] = fmaxf(s, 0.0f);
    }
    __syncthreads();
    if (t < 32) {
        float s = fc1_b[t];
        for (int k = 0; k < 64; k++) s += z1[k] * fc1_w[k * 32 + t];
        z2[t] = s;
    }
    __syncthreads();
    if (t < 16) {
        float s = fc2_b[t];
        for (int k = 0; k < 32; k++) s += z2[k] * fc2_w[k * 16 + t];
        z3[t] = s;
    }
    __syncthreads();
    if (t < 8) {
        float s = fc3_b[t];
        for (int k = 0; k < 16; k++) s += z3[k] * fc3_w[k * 8 + t];
        z4[t] = s;
    }
    __syncthreads();
    if (t < 2) {
        float s = fc4_b[t];
        for (int k = 0; k < 8; k++) s += z4[k] * fc4_w[k * 2 + t];
        z5[t] = s;
    }
    __syncthreads();
    if (t == 0) out[g] = z5[0] * fc5_w[0] + z5[1] * fc5_w[1] + fc5_b[0];
}

// ---------------- launch ----------------
extern "C" void kernel_launch(void* const* d_in, const int* in_sizes, int n_in,
                              void* d_out, int out_size) {
    const float* x      = (const float*)d_in[0];
    const int*   src    = (const int*)d_in[1];
    const int*   dst    = (const int*)d_in[2];
    const int*   batch  = (const int*)d_in[3];
    const float* g1_w1  = (const float*)d_in[4];
    const float* g1_b1  = (const float*)d_in[5];
    const float* g1_w2  = (const float*)d_in[6];
    const float* g1_b2  = (const float*)d_in[7];
    const float* bn1_g  = (const float*)d_in[8];
    const float* bn1_b  = (const float*)d_in[9];
    const float* g2_w1  = (const float*)d_in[10];
    const float* g2_b1  = (const float*)d_in[11];
    const float* g2_w2  = (const float*)d_in[12];
    const float* g2_b2  = (const float*)d_in[13];
    const float* bn2_g  = (const float*)d_in[14];
    const float* bn2_b  = (const float*)d_in[15];
    const float* fcxd_w = (const float*)d_in[16];
    const float* fcxd_b = (const float*)d_in[17];
    const float* fc1_w  = (const float*)d_in[18];
    const float* fc1_b  = (const float*)d_in[19];
    const float* fc2_w  = (const float*)d_in[20];
    const float* fc2_b  = (const float*)d_in[21];
    const float* fc3_w  = (const float*)d_in[22];
    const float* fc3_b  = (const float*)d_in[23];
    const float* fc4_w  = (const float*)d_in[24];
    const float* fc4_b  = (const float*)d_in[25];
    const float* fc5_w  = (const float*)d_in[26];
    const float* fc5_b  = (const float*)d_in[27];
    float* out = (float*)d_out;

    const int E = in_sizes[1];
    const int M = NN;

    // resolve device scratch addresses
    float *A, *T, *H, *B, *T2, *H2;
    double *sum1, *sq1, *sum2, *sq2;
    cudaGetSymbolAddress((void**)&A,   g_A);
    cudaGetSymbolAddress((void**)&T,   g_T);
    cudaGetSymbolAddress((void**)&H,   g_H);
    cudaGetSymbolAddress((void**)&B,   g_B);
    cudaGetSymbolAddress((void**)&T2,  g_T2);
    cudaGetSymbolAddress((void**)&H2,  g_H2);
    cudaGetSymbolAddress((void**)&sum1, g_sum1);
    cudaGetSymbolAddress((void**)&sq1,  g_sq1);
    cudaGetSymbolAddress((void**)&sum2, g_sum2);
    cudaGetSymbolAddress((void**)&sq2,  g_sq2);

    const int n4 = (M * FI) / 4;

    // 0. zero stats + pool
    zero_scratch_kernel<<<(NG * DM + 255) / 256, 256>>>();

    // ---- GIN layer 1 ----
    copy4_kernel<<<(n4 + 255) / 256, 256>>>((float4*)A, (const float4*)x, n4);
    scatter_add112_kernel<<<(E * 28 + 255) / 256, 256>>>(x, src, dst, A, E);
    gemm_bias_relu_kernel<FI, FI, 8><<<(M + 7) / 8, FI>>>(A, g1_w1, g1_b1, T, M);
    gemm_bias_relu_kernel<FI, FI, 8><<<(M + 7) / 8, FI>>>(T, g1_w2, g1_b2, H, M);
    bn_stats_kernel<FI><<<512, FI>>>(H, M, sum1, sq1);
    bn_norm_kernel<FI><<<(M * FI + 255) / 256, 256>>>(H, M, sum1, sq1, bn1_g, bn1_b);

    // ---- GIN layer 2 ----
    copy4_kernel<<<(n4 + 255) / 256, 256>>>((float4*)B, (const float4*)H, n4);
    scatter_add112_kernel<<<(E * 28 + 255) / 256, 256>>>(H, src, dst, B, E);
    gemm_bias_relu_kernel<FI, DM, 16><<<(M + 15) / 16, DM>>>(B, g2_w1, g2_b1, T2, M);
    gemm_bias_relu_kernel<DM, DM, 32><<<(M + 31) / 32, DM>>>(T2, g2_w2, g2_b2, H2, M);
    bn_stats_kernel<DM><<<512, DM>>>(H2, M, sum2, sq2);
    bn_norm_kernel<DM><<<(M * DM + 255) / 256, 256>>>(H2, M, sum2, sq2, bn2_g, bn2_b);

    // ---- pool + head ----
    pool_kernel<<<(M * DM + 255) / 256, 256>>>(H2, batch, M);
    head_kernel<<<NG, 64>>>(fcxd_w, fcxd_b, fc1_w, fc1_b, fc2_w, fc2_b,
                            fc3_w, fc3_b, fc4_w, fc4_b, fc5_w, fc5_b, out);
}

// round 2
// speedup vs baseline: 1.2073x; 1.2073x over previous
#include <cuda_runtime.h>
#include <cuda_bf16.h>
#include <cstdint>

// ---------------- problem constants ----------------
#define NN 50000      // nodes
#define NE 800000     // edges
#define FI 112        // feature dim layer1
#define DM 32         // dim layer2
#define NG 256        // graphs
#define BN_EPS 1e-5f

// ---------------- device scratch (no allocs allowed) ----------------
__device__ float  g_A [NN * FI];   // x + agg1
__device__ float  g_T [NN * FI];   // MLP intermediate
__device__ float  g_H [NN * FI];   // MLP1 out / bn1 (in place)
__device__ float  g_B [NN * FI];   // hn + agg2
__device__ float  g_T2[NN * DM];
__device__ float  g_H2[NN * DM];
__device__ double g_sum1[FI], g_sq1[FI];
__device__ double g_sum2[DM], g_sq2[DM];
__device__ float  g_pool[NG * DM];
// CSR scratch
__device__ int    g_deg[NN];
__device__ int    g_rowptr[NN + 1];
__device__ int    g_cursor[NN];
__device__ int    g_col[NE];

// ---------------- zero scratch ----------------
__global__ void zero_kernel() {
    int t = blockIdx.x * blockDim.x + threadIdx.x;
    if (t < NN) g_deg[t] = 0;
    if (t < FI) { g_sum1[t] = 0.0; g_sq1[t] = 0.0; }
    if (t < DM) { g_sum2[t] = 0.0; g_sq2[t] = 0.0; }
    if (t < NG * DM) g_pool[t] = 0.0f;
}

// ---------------- CSR build ----------------
__global__ void hist_kernel(const int* __restrict__ dst, int E) {
    int e = blockIdx.x * blockDim.x + threadIdx.x;
    if (e < E) atomicAdd(&g_deg[dst[e]], 1);
}

__global__ void scan_kernel() {
    // single block, 1024 threads; exclusive scan of g_deg into g_rowptr/g_cursor
    const int CH = (NN + 1023) >> 10;   // 49
    int t = threadIdx.x;
    int base = t * CH;
    int s = 0;
    for (int i = 0; i < CH; i++) {
        int idx = base + i;
        if (idx < NN) s += g_deg[idx];
    }
    int lane = t & 31, wid = t >> 5;
    int v = s;
#pragma unroll
    for (int d = 1; d < 32; d <<= 1) {
        int n = __shfl_up_sync(0xffffffffu, v, d);
        if (lane >= d) v += n;
    }
    __shared__ int wsum[32];
    if (lane == 31) wsum[wid] = v;
    __syncthreads();
    if (wid == 0) {
        int w = wsum[lane];
#pragma unroll
        for (int d = 1; d < 32; d <<= 1) {
            int n = __shfl_up_sync(0xffffffffu, w, d);
            if (lane >= d) w += n;
        }
        wsum[lane] = w;
    }
    __syncthreads();
    int excl = v - s + (wid ? wsum[wid - 1] : 0);
    int run = excl;
    for (int i = 0; i < CH; i++) {
        int idx = base + i;
        if (idx < NN) {
            g_rowptr[idx] = run;
            g_cursor[idx] = run;
            run += g_deg[idx];
        }
    }
    if (t == 1023) g_rowptr[NN] = excl;  // all elements are before this thread's (empty) chunk
}

__global__ void fill_kernel(const int* __restrict__ src, const int* __restrict__ dst, int E) {
    int e = blockIdx.x * blockDim.x + threadIdx.x;
    if (e < E) {
        int p = atomicAdd(&g_cursor[dst[e]], 1);
        g_col[p] = src[e];
    }
}

// ---------------- gather aggregation: out[i] = base[i] + sum_{e in CSR(i)} X[col[e]] ----------------
__global__ void agg112_kernel(const float* __restrict__ X, const float* __restrict__ base,
                              float* __restrict__ out) {
    int node = blockIdx.x;
    int f = threadIdx.x;                  // 0..111
    int beg = __ldg(&g_rowptr[node]);
    int end = __ldg(&g_rowptr[node + 1]);
    float acc = base[(size_t)node * FI + f];
    float a0 = 0.f, a1 = 0.f, a2 = 0.f, a3 = 0.f;
    int e = beg;
    for (; e + 4 <= end; e += 4) {
        int s0 = __ldg(&g_col[e]);
        int s1 = __ldg(&g_col[e + 1]);
        int s2 = __ldg(&g_col[e + 2]);
        int s3 = __ldg(&g_col[e + 3]);
        a0 += X[(size_t)s0 * FI + f];
        a1 += X[(size_t)s1 * FI + f];
        a2 += X[(size_t)s2 * FI + f];
        a3 += X[(size_t)s3 * FI + f];
    }
    for (; e < end; e++) acc += X[(size_t)__ldg(&g_col[e]) * FI + f];
    out[(size_t)node * FI + f] = acc + ((a0 + a1) + (a2 + a3));
}

// ---------------- tiled 112x112 GEMM with packed f32x2 FMA, ReLU epilogue ----------------
// C[M,112] = relu(A[M,112] @ W[112,112] + b)
__global__ __launch_bounds__(256) void gemm112_kernel(const float* __restrict__ A,
                                                      const float* __restrict__ W,
                                                      const float* __restrict__ bias,
                                                      float* __restrict__ C, int M) {
    __shared__ float As[16][68];       // [kk][row], padded
    __shared__ float Ws[16 * 112];     // [kk][col]
    const int tid = threadIdx.x;
    const int tr = tid >> 4;           // 0..15 -> rows tr*4 .. tr*4+3
    const int tc = tid & 15;           // 0..15 -> cols tc*7 .. tc*7+6
    const int row0 = blockIdx.x * 64;

    unsigned long long acc01[7], acc23[7];
#pragma unroll
    for (int j = 0; j < 7; j++) { acc01[j] = 0ull; acc23[j] = 0ull; }

    for (int kc = 0; kc < 112; kc += 16) {
#pragma unroll
        for (int i = 0; i < 4; i++) {
            int idx = tid + i * 256;
            int kk = idx & 15, r = idx >> 4;
            int gr = row0 + r;
            As[kk][r] = (gr < M) ? A[(size_t)gr * 112 + kc + kk] : 0.0f;
        }
#pragma unroll
        for (int i = 0; i < 7; i++) {
            int idx = tid + i * 256;
            int c = idx % 112, kk = idx / 112;
            Ws[kk * 112 + c] = W[(size_t)(kc + kk) * 112 + c];
        }
        __syncthreads();
#pragma unroll
        for (int kk = 0; kk < 16; kk++) {
            float4 av = *reinterpret_cast<const float4*>(&As[kk][tr * 4]);
            unsigned long long a01, a23;
            asm("mov.b64 %0, {%1, %2};" : "=l"(a01) : "f"(av.x), "f"(av.y));
            asm("mov.b64 %0, {%1, %2};" : "=l"(a23) : "f"(av.z), "f"(av.w));
#pragma unroll
            for (int j = 0; j < 7; j++) {
                float w = Ws[kk * 112 + tc * 7 + j];
                unsigned long long wp;
                asm("mov.b64 %0, {%1, %1};" : "=l"(wp) : "f"(w));
                asm("fma.rn.f32x2 %0, %1, %2, %0;" : "+l"(acc01[j]) : "l"(a01), "l"(wp));
                asm("fma.rn.f32x2 %0, %1, %2, %0;" : "+l"(acc23[j]) : "l"(a23), "l"(wp));
            }
        }
        __syncthreads();
    }
#pragma unroll
    for (int j = 0; j < 7; j++) {
        int c = tc * 7 + j;
        float b = __ldg(&bias[c]);
        float lo, hi;
        int r0 = row0 + tr * 4;
        asm("mov.b64 {%0, %1}, %2;" : "=f"(lo), "=f"(hi) : "l"(acc01[j]));
        if (r0 < M)     C[(size_t)r0 * 112 + c]       = fmaxf(lo + b, 0.f);
        if (r0 + 1 < M) C[(size_t)(r0 + 1) * 112 + c] = fmaxf(hi + b, 0.f);
        asm("mov.b64 {%0, %1}, %2;" : "=f"(lo), "=f"(hi) : "l"(acc23[j]));
        if (r0 + 2 < M) C[(size_t)(r0 + 2) * 112 + c] = fmaxf(lo + b, 0.f);
        if (r0 + 3 < M) C[(size_t)(r0 + 3) * 112 + c] = fmaxf(hi + b, 0.f);
    }
}

// ---------------- small GEMM: C = relu(A[M,K] @ W[K,N] + b), blockDim = N ----------------
template<int K, int N, int ROWS>
__global__ void gemm_bias_relu_kernel(const float* __restrict__ A,
                                      const float* __restrict__ W,
                                      const float* __restrict__ bias,
                                      float* __restrict__ C, int M) {
    __shared__ float As[ROWS][K];
    const int f = threadIdx.x;
    const int row0 = blockIdx.x * ROWS;
    for (int i = f; i < ROWS * K; i += N) {
        int r = i / K, k = i % K;
        As[r][k] = (row0 + r < M) ? A[(size_t)(row0 + r) * K + k] : 0.0f;
    }
    __syncthreads();
    float acc[ROWS];
#pragma unroll
    for (int r = 0; r < ROWS; r++) acc[r] = 0.0f;
#pragma unroll 4
    for (int k = 0; k < K; k++) {
        float w = __ldg(&W[k * N + f]);
#pragma unroll
        for (int r = 0; r < ROWS; r++) acc[r] += As[r][k] * w;
    }
    float bb = __ldg(&bias[f]);
#pragma unroll
    for (int r = 0; r < ROWS; r++)
        if (row0 + r < M)
            C[(size_t)(row0 + r) * N + f] = fmaxf(acc[r] + bb, 0.0f);
}

// ---------------- BatchNorm stats (double accumulation) ----------------
template<int N>
__global__ void bn_stats_kernel(const float* __restrict__ H, int M,
                                double* __restrict__ sum, double* __restrict__ sq) {
    int f = threadIdx.x;
    double s = 0.0, s2 = 0.0;
    for (int i = blockIdx.x; i < M; i += gridDim.x) {
        double v = (double)H[(size_t)i * N + f];
        s += v;
        s2 += v * v;
    }
    atomicAdd(&sum[f], s);
    atomicAdd(&sq[f], s2);
}

template<int N>
__global__ void bn_norm_kernel(float* __restrict__ H, int M,
                               const double* __restrict__ sum, const double* __restrict__ sq,
                               const float* __restrict__ gamma, const float* __restrict__ beta) {
    int idx = blockIdx.x * blockDim.x + threadIdx.x;
    if (idx >= M * N) return;
    int f = idx % N;
    double m = sum[f] / (double)M;
    double var = sq[f] / (double)M - m * m;
    float rs = rsqrtf((float)var + BN_EPS);
    float v = H[idx];
    H[idx] = ((v - (float)m) * rs) * __ldg(&gamma[f]) + __ldg(&beta[f]);
}

// ---------------- global add pool ----------------
__global__ void pool_kernel(const float* __restrict__ H2, const int* __restrict__ batch, int M) {
    int idx = blockIdx.x * blockDim.x + threadIdx.x;
    if (idx >= M * DM) return;
    int i = idx / DM;
    int f = idx % DM;
    atomicAdd(&g_pool[__ldg(&batch[i]) * DM + f], H2[idx]);
}

// ---------------- dense head ----------------
__global__ void head_kernel(const float* __restrict__ fcxd_w, const float* __restrict__ fcxd_b,
                            const float* __restrict__ fc1_w,  const float* __restrict__ fc1_b,
                            const float* __restrict__ fc2_w,  const float* __restrict__ fc2_b,
                            const float* __restrict__ fc3_w,  const float* __restrict__ fc3_b,
                            const float* __restrict__ fc4_w,  const float* __restrict__ fc4_b,
                            const float* __restrict__ fc5_w,  const float* __restrict__ fc5_b,
                            float* __restrict__ out) {
    __shared__ float p[DM], z1[64], z2[32], z3[16], z4[8], z5[2];
    int g = blockIdx.x, t = threadIdx.x;
    if (t < DM) p[t] = g_pool[g * DM + t];
    __syncthreads();
    if (t < 64) {
        float s = fcxd_b[t];
        for (int k = 0; k < 32; k++) s += p[k] * fcxd_w[k * 64 + t];
        z1[t] = fmaxf(s, 0.0f);
    }
    __syncthreads();
    if (t < 32) {
        float s = fc1_b[t];
        for (int k = 0; k < 64; k++) s += z1[k] * fc1_w[k * 32 + t];
        z2[t] = s;
    }
    __syncthreads();
    if (t < 16) {
        float s = fc2_b[t];
        for (int k = 0; k < 32; k++) s += z2[k] * fc2_w[k * 16 + t];
        z3[t] = s;
    }
    __syncthreads();
    if (t < 8) {
        float s = fc3_b[t];
        for (int k = 0; k < 16; k++) s += z3[k] * fc3_w[k * 8 + t];
        z4[t] = s;
    }
    __syncthreads();
    if (t < 2) {
        float s = fc4_b[t];
        for (int k = 0; k < 8; k++) s += z4[k] * fc4_w[k * 2 + t];
        z5[t] = s;
    }
    __syncthreads();
    if (t == 0) out[g] = z5[0] * fc5_w[0] + z5[1] * fc5_w[1] + fc5_b[0];
}

// ---------------- launch ----------------
extern "C" void kernel_launch(void* const* d_in, const int* in_sizes, int n_in,
                              void* d_out, int out_size) {
    const float* x      = (const float*)d_in[0];
    const int*   src    = (const int*)d_in[1];
    const int*   dst    = (const int*)d_in[2];
    const int*   batch  = (const int*)d_in[3];
    const float* g1_w1  = (const float*)d_in[4];
    const float* g1_b1  = (const float*)d_in[5];
    const float* g1_w2  = (const float*)d_in[6];
    const float* g1_b2  = (const float*)d_in[7];
    const float* bn1_g  = (const float*)d_in[8];
    const float* bn1_b  = (const float*)d_in[9];
    const float* g2_w1  = (const float*)d_in[10];
    const float* g2_b1  = (const float*)d_in[11];
    const float* g2_w2  = (const float*)d_in[12];
    const float* g2_b2  = (const float*)d_in[13];
    const float* bn2_g  = (const float*)d_in[14];
    const float* bn2_b  = (const float*)d_in[15];
    const float* fcxd_w = (const float*)d_in[16];
    const float* fcxd_b = (const float*)d_in[17];
    const float* fc1_w  = (const float*)d_in[18];
    const float* fc1_b  = (const float*)d_in[19];
    const float* fc2_w  = (const float*)d_in[20];
    const float* fc2_b  = (const float*)d_in[21];
    const float* fc3_w  = (const float*)d_in[22];
    const float* fc3_b  = (const float*)d_in[23];
    const float* fc4_w  = (const float*)d_in[24];
    const float* fc4_b  = (const float*)d_in[25];
    const float* fc5_w  = (const float*)d_in[26];
    const float* fc5_b  = (const float*)d_in[27];
    float* out = (float*)d_out;

    const int E = in_sizes[1];
    const int M = NN;

    float *A, *T, *H, *B, *T2, *H2;
    double *sum1, *sq1, *sum2, *sq2;
    cudaGetSymbolAddress((void**)&A,   g_A);
    cudaGetSymbolAddress((void**)&T,   g_T);
    cudaGetSymbolAddress((void**)&H,   g_H);
    cudaGetSymbolAddress((void**)&B,   g_B);
    cudaGetSymbolAddress((void**)&T2,  g_T2);
    cudaGetSymbolAddress((void**)&H2,  g_H2);
    cudaGetSymbolAddress((void**)&sum1, g_sum1);
    cudaGetSymbolAddress((void**)&sq1,  g_sq1);
    cudaGetSymbolAddress((void**)&sum2, g_sum2);
    cudaGetSymbolAddress((void**)&sq2,  g_sq2);

    // 0. zero scratch + CSR build (reused by both layers)
    zero_kernel<<<(NN + 255) / 256, 256>>>();
    hist_kernel<<<(E + 255) / 256, 256>>>(dst, E);
    scan_kernel<<<1, 1024>>>();
    fill_kernel<<<(E + 255) / 256, 256>>>(src, dst, E);

    // ---- GIN layer 1 ----
    agg112_kernel<<<NN, FI>>>(x, x, A);
    gemm112_kernel<<<(M + 63) / 64, 256>>>(A, g1_w1, g1_b1, T, M);
    gemm112_kernel<<<(M + 63) / 64, 256>>>(T, g1_w2, g1_b2, H, M);
    bn_stats_kernel<FI><<<512, FI>>>(H, M, sum1, sq1);
    bn_norm_kernel<FI><<<(M * FI + 255) / 256, 256>>>(H, M, sum1, sq1, bn1_g, bn1_b);

    // ---- GIN layer 2 ----
    agg112_kernel<<<NN, FI>>>(H, H, B);
    gemm_bias_relu_kernel<FI, DM, 16><<<(M + 15) / 16, DM>>>(B, g2_w1, g2_b1, T2, M);
    gemm_bias_relu_kernel<DM, DM, 32><<<(M + 31) / 32, DM>>>(T2, g2_w2, g2_b2, H2, M);
    bn_stats_kernel<DM><<<512, DM>>>(H2, M, sum2, sq2);
    bn_norm_kernel<DM><<<(M * DM + 255) / 256, 256>>>(H2, M, sum2, sq2, bn2_g, bn2_b);

    // ---- pool + head ----
    pool_kernel<<<(M * DM + 255) / 256, 256>>>(H2, batch, M);
    head_kernel<<<NG, 64>>>(fcxd_w, fcxd_b, fc1_w, fc1_b, fc2_w, fc2_b,
                            fc3_w, fc3_b, fc4_w, fc4_b, fc5_w, fc5_b, out);
}

// round 3
// speedup vs baseline: 1.9483x; 1.6138x over previous
#include <cuda_runtime.h>
#include <cuda_bf16.h>
#include <cstdint>

#define NN 50000
#define NE 800000
#define FI 112
#define DM 32
#define NG 256
#define BN_EPS 1e-5f

typedef unsigned long long u64;

// ---------------- device scratch ----------------
__device__ float  g_A [NN * FI];
__device__ float  g_T [NN * FI];
__device__ float  g_H [NN * FI];
__device__ float  g_B [NN * FI];
__device__ float  g_H2[NN * DM];
__device__ double g_sum1[FI], g_sq1[FI];
__device__ double g_sum2[DM], g_sq2[DM];
__device__ float  g_a1[FI], g_c1[FI];
__device__ float  g_a2[DM], g_c2[DM];
__device__ float  g_pool[NG * DM];
__device__ int    g_cnt[NG];
__device__ int    g_deg[NN];
__device__ int    g_rowptr[NN + 1];
__device__ int    g_cursor[NN];
__device__ int    g_col[NE];

// ---------------- zero ----------------
__global__ void zero_kernel() {
    int t = blockIdx.x * blockDim.x + threadIdx.x;
    if (t < NN) g_deg[t] = 0;
    if (t < FI) { g_sum1[t] = 0.0; g_sq1[t] = 0.0; }
    if (t < DM) { g_sum2[t] = 0.0; g_sq2[t] = 0.0; }
    if (t < NG * DM) g_pool[t] = 0.0f;
    if (t < NG) g_cnt[t] = 0;
}

// ---------------- CSR build ----------------
__global__ void hist_kernel(const int* __restrict__ dst, int E) {
    int e = blockIdx.x * blockDim.x + threadIdx.x;
    if (e < E) atomicAdd(&g_deg[dst[e]], 1);
}

__global__ void scan_kernel() {
    const int CH = (NN + 1023) >> 10;
    int t = threadIdx.x;
    int base = t * CH;
    int s = 0;
    for (int i = 0; i < CH; i++) {
        int idx = base + i;
        if (idx < NN) s += g_deg[idx];
    }
    int lane = t & 31, wid = t >> 5;
    int v = s;
#pragma unroll
    for (int d = 1; d < 32; d <<= 1) {
        int n = __shfl_up_sync(0xffffffffu, v, d);
        if (lane >= d) v += n;
    }
    __shared__ int wsum[32];
    if (lane == 31) wsum[wid] = v;
    __syncthreads();
    if (wid == 0) {
        int w = wsum[lane];
#pragma unroll
        for (int d = 1; d < 32; d <<= 1) {
            int n = __shfl_up_sync(0xffffffffu, w, d);
            if (lane >= d) w += n;
        }
        wsum[lane] = w;
    }
    __syncthreads();
    int excl = v - s + (wid ? wsum[wid - 1] : 0);
    int run = excl;
    for (int i = 0; i < CH; i++) {
        int idx = base + i;
        if (idx < NN) {
            g_rowptr[idx] = run;
            g_cursor[idx] = run;
            run += g_deg[idx];
        }
    }
    if (t == 1023) g_rowptr[NN] = excl;
}

__global__ void fill_kernel(const int* __restrict__ src, const int* __restrict__ dst, int E) {
    int e = blockIdx.x * blockDim.x + threadIdx.x;
    if (e < E) {
        int p = atomicAdd(&g_cursor[dst[e]], 1);
        g_col[p] = src[e];
    }
}

// ---------------- warp-per-node float4 gather aggregation ----------------
// AFF=0: out = X_i + sum_j X_j
// AFF=1: out = a * (X_i + sum_j X_j) + (1+deg) * c
template<int AFF>
__global__ __launch_bounds__(256) void agg_kernel(const float* __restrict__ X,
                                                  float* __restrict__ out,
                                                  const float* __restrict__ av,
                                                  const float* __restrict__ cv) {
    int node = blockIdx.x * 8 + (threadIdx.x >> 5);
    if (node >= NN) return;
    int lane = threadIdx.x & 31;
    int beg = __ldg(&g_rowptr[node]);
    int end = __ldg(&g_rowptr[node + 1]);
    bool act = lane < 28;
    size_t foff = (size_t)(lane << 2);

    float4 acc  = make_float4(0.f, 0.f, 0.f, 0.f);
    float4 acc1 = acc, acc2 = acc, acc3 = acc;
    if (act) acc = *reinterpret_cast<const float4*>(X + (size_t)node * FI + foff);

    int e = beg;
    for (; e + 4 <= end; e += 4) {
        int s0 = __ldg(&g_col[e + 0]);
        int s1 = __ldg(&g_col[e + 1]);
        int s2 = __ldg(&g_col[e + 2]);
        int s3 = __ldg(&g_col[e + 3]);
        if (act) {
            float4 v0 = *reinterpret_cast<const float4*>(X + (size_t)s0 * FI + foff);
            float4 v1 = *reinterpret_cast<const float4*>(X + (size_t)s1 * FI + foff);
            float4 v2 = *reinterpret_cast<const float4*>(X + (size_t)s2 * FI + foff);
            float4 v3 = *reinterpret_cast<const float4*>(X + (size_t)s3 * FI + foff);
            acc.x += v0.x; acc.y += v0.y; acc.z += v0.z; acc.w += v0.w;
            acc1.x += v1.x; acc1.y += v1.y; acc1.z += v1.z; acc1.w += v1.w;
            acc2.x += v2.x; acc2.y += v2.y; acc2.z += v2.z; acc2.w += v2.w;
            acc3.x += v3.x; acc3.y += v3.y; acc3.z += v3.z; acc3.w += v3.w;
        }
    }
    for (; e < end; e++) {
        int s = __ldg(&g_col[e]);
        if (act) {
            float4 v = *reinterpret_cast<const float4*>(X + (size_t)s * FI + foff);
            acc.x += v.x; acc.y += v.y; acc.z += v.z; acc.w += v.w;
        }
    }
    if (!act) return;
    float4 r;
    r.x = (acc.x + acc1.x) + (acc2.x + acc3.x);
    r.y = (acc.y + acc1.y) + (acc2.y + acc3.y);
    r.z = (acc.z + acc1.z) + (acc2.z + acc3.z);
    r.w = (acc.w + acc1.w) + (acc2.w + acc3.w);
    if (AFF) {
        float dp1 = (float)(1 + end - beg);
        float4 a = *reinterpret_cast<const float4*>(av + foff);
        float4 c = *reinterpret_cast<const float4*>(cv + foff);
        r.x = a.x * r.x + dp1 * c.x;
        r.y = a.y * r.y + dp1 * c.y;
        r.z = a.z * r.z + dp1 * c.z;
        r.w = a.w * r.w + dp1 * c.w;
    }
    *reinterpret_cast<float4*>(out + (size_t)node * FI + foff) = r;
}

// ---------------- 112x112 GEMM, f32x2, pre-duplicated W pairs ----------------
__global__ __launch_bounds__(256) void gemm112_kernel(const float* __restrict__ A,
                                                      const float* __restrict__ W,
                                                      const float* __restrict__ bias,
                                                      float* __restrict__ C, int M) {
    __shared__ __align__(16) float  As[16][68];
    __shared__ __align__(16) float2 Wd[16][112];
    const int tid = threadIdx.x;
    const int tr = tid >> 4;   // rows tr*4..+3
    const int tc = tid & 15;   // cols tc*7..+6
    const int row0 = blockIdx.x * 64;

    u64 acc01[7], acc23[7];
#pragma unroll
    for (int j = 0; j < 7; j++) { acc01[j] = 0ull; acc23[j] = 0ull; }

    for (int kc = 0; kc < 112; kc += 16) {
        {   // A tile: 64 rows x 16 k, transpose to k-major
            int r = tid >> 2, k4 = (tid & 3) << 2;
            float4 v = make_float4(0.f, 0.f, 0.f, 0.f);
            if (row0 + r < M)
                v = *reinterpret_cast<const float4*>(A + (size_t)(row0 + r) * 112 + kc + k4);
            As[k4 + 0][r] = v.x;
            As[k4 + 1][r] = v.y;
            As[k4 + 2][r] = v.z;
            As[k4 + 3][r] = v.w;
        }
#pragma unroll
        for (int i = 0; i < 7; i++) {
            int idx = tid + i * 256;
            int c = idx % 112, kk = idx / 112;
            float w = W[(size_t)(kc + kk) * 112 + c];
            Wd[kk][c] = make_float2(w, w);
        }
        __syncthreads();
#pragma unroll
        for (int kk = 0; kk < 16; kk++) {
            float4 av = *reinterpret_cast<const float4*>(&As[kk][tr * 4]);
            u64 a01, a23;
            asm("mov.b64 %0, {%1, %2};" : "=l"(a01) : "f"(av.x), "f"(av.y));
            asm("mov.b64 %0, {%1, %2};" : "=l"(a23) : "f"(av.z), "f"(av.w));
#pragma unroll
            for (int j = 0; j < 7; j++) {
                u64 wp = *reinterpret_cast<const u64*>(&Wd[kk][tc * 7 + j]);
                asm("fma.rn.f32x2 %0, %1, %2, %0;" : "+l"(acc01[j]) : "l"(a01), "l"(wp));
                asm("fma.rn.f32x2 %0, %1, %2, %0;" : "+l"(acc23[j]) : "l"(a23), "l"(wp));
            }
        }
        __syncthreads();
    }
#pragma unroll
    for (int j = 0; j < 7; j++) {
        int c = tc * 7 + j;
        float b = __ldg(&bias[c]);
        float lo, hi;
        int r0 = row0 + tr * 4;
        asm("mov.b64 {%0, %1}, %2;" : "=f"(lo), "=f"(hi) : "l"(acc01[j]));
        if (r0 < M)     C[(size_t)r0 * 112 + c]       = fmaxf(lo + b, 0.f);
        if (r0 + 1 < M) C[(size_t)(r0 + 1) * 112 + c] = fmaxf(hi + b, 0.f);
        asm("mov.b64 {%0, %1}, %2;" : "=f"(lo), "=f"(hi) : "l"(acc23[j]));
        if (r0 + 2 < M) C[(size_t)(r0 + 2) * 112 + c] = fmaxf(lo + b, 0.f);
        if (r0 + 3 < M) C[(size_t)(r0 + 3) * 112 + c] = fmaxf(hi + b, 0.f);
    }
}

// ---------------- fused layer-2 MLP: H2 = relu(relu(B W1 + b1) W2 + b2) ----------------
// k-major smem tiles with xor-16 swizzle; Z reuses B's smem region.
#define SWZ(k, r) (((((r) >> 2) ^ ((k) & 15)) << 2) | ((r) & 3))
__global__ __launch_bounds__(256) void mlp2_kernel(const float* __restrict__ B,
                                                   const float* __restrict__ W1,
                                                   const float* __restrict__ b1,
                                                   const float* __restrict__ W2,
                                                   const float* __restrict__ b2,
                                                   float* __restrict__ H2, int M) {
    __shared__ __align__(16) float Bs[112 * 64];   // also reused as Zs[32*64]
    __shared__ __align__(16) float W1s[112][32];
    __shared__ __align__(16) float W2s[32][32];
    const int tid = threadIdx.x;
    const int tr = tid >> 4;   // rows tr*4..+3
    const int tc = tid & 15;   // cols tc*2, tc*2+1
    const int row0 = blockIdx.x * 64;

    // loads
    for (int idx = tid; idx < 112 * 32; idx += 256) W1s[idx >> 5][idx & 31] = W1[idx];
    for (int idx = tid; idx < 32 * 32; idx += 256)  W2s[idx >> 5][idx & 31] = W2[idx];
    for (int idx = tid; idx < 64 * 112; idx += 256) {
        int k = idx % 112, r = idx / 112;
        float v = (row0 + r < M) ? B[(size_t)(row0 + r) * 112 + k] : 0.f;
        Bs[k * 64 + SWZ(k, r)] = v;
    }
    __syncthreads();

    // phase 1: Z = relu(B @ W1 + b1), thread: 4 rows x 2 cols
    u64 z01[2], z23[2];
#pragma unroll
    for (int j = 0; j < 2; j++) { z01[j] = 0ull; z23[j] = 0ull; }
    for (int k = 0; k < 112; k++) {
        int grp = (tr ^ (k & 15)) << 2;
        float4 av = *reinterpret_cast<const float4*>(&Bs[k * 64 + grp]);
        u64 a01, a23;
        asm("mov.b64 %0, {%1, %2};" : "=l"(a01) : "f"(av.x), "f"(av.y));
        asm("mov.b64 %0, {%1, %2};" : "=l"(a23) : "f"(av.z), "f"(av.w));
        float2 w = *reinterpret_cast<const float2*>(&W1s[k][tc * 2]);
        u64 w0, w1;
        asm("mov.b64 %0, {%1, %1};" : "=l"(w0) : "f"(w.x));
        asm("mov.b64 %0, {%1, %1};" : "=l"(w1) : "f"(w.y));
        asm("fma.rn.f32x2 %0, %1, %2, %0;" : "+l"(z01[0]) : "l"(a01), "l"(w0));
        asm("fma.rn.f32x2 %0, %1, %2, %0;" : "+l"(z23[0]) : "l"(a23), "l"(w0));
        asm("fma.rn.f32x2 %0, %1, %2, %0;" : "+l"(z01[1]) : "l"(a01), "l"(w1));
        asm("fma.rn.f32x2 %0, %1, %2, %0;" : "+l"(z23[1]) : "l"(a23), "l"(w1));
    }
    __syncthreads();   // Bs fully consumed; reuse as Zs

    float* Zs = Bs;
#pragma unroll
    for (int j = 0; j < 2; j++) {
        int c = tc * 2 + j;
        float bb = __ldg(&b1[c]);
        float v0, v1, v2, v3;
        asm("mov.b64 {%0, %1}, %2;" : "=f"(v0), "=f"(v1) : "l"(z01[j]));
        asm("mov.b64 {%0, %1}, %2;" : "=f"(v2), "=f"(v3) : "l"(z23[j]));
        int grp = (tr ^ (c & 15)) << 2;
        float4* p = reinterpret_cast<float4*>(&Zs[c * 64 + grp]);
        *p = make_float4(fmaxf(v0 + bb, 0.f), fmaxf(v1 + bb, 0.f),
                         fmaxf(v2 + bb, 0.f), fmaxf(v3 + bb, 0.f));
    }
    __syncthreads();

    // phase 2: H2 = relu(Z @ W2 + b2)
    u64 h01[2], h23[2];
#pragma unroll
    for (int j = 0; j < 2; j++) { h01[j] = 0ull; h23[j] = 0ull; }
#pragma unroll
    for (int k = 0; k < 32; k++) {
        int grp = (tr ^ (k & 15)) << 2;
        float4 av = *reinterpret_cast<const float4*>(&Zs[k * 64 + grp]);
        u64 a01, a23;
        asm("mov.b64 %0, {%1, %2};" : "=l"(a01) : "f"(av.x), "f"(av.y));
        asm("mov.b64 %0, {%1, %2};" : "=l"(a23) : "f"(av.z), "f"(av.w));
        float2 w = *reinterpret_cast<const float2*>(&W2s[k][tc * 2]);
        u64 w0, w1;
        asm("mov.b64 %0, {%1, %1};" : "=l"(w0) : "f"(w.x));
        asm("mov.b64 %0, {%1, %1};" : "=l"(w1) : "f"(w.y));
        asm("fma.rn.f32x2 %0, %1, %2, %0;" : "+l"(h01[0]) : "l"(a01), "l"(w0));
        asm("fma.rn.f32x2 %0, %1, %2, %0;" : "+l"(h23[0]) : "l"(a23), "l"(w0));
        asm("fma.rn.f32x2 %0, %1, %2, %0;" : "+l"(h01[1]) : "l"(a01), "l"(w1));
        asm("fma.rn.f32x2 %0, %1, %2, %0;" : "+l"(h23[1]) : "l"(a23), "l"(w1));
    }
    // epilogue: store as float2 per row (cols 2tc,2tc+1)
    float b20 = __ldg(&b2[tc * 2]);
    float b21 = __ldg(&b2[tc * 2 + 1]);
    float r0c0, r1c0, r2c0, r3c0, r0c1, r1c1, r2c1, r3c1;
    asm("mov.b64 {%0, %1}, %2;" : "=f"(r0c0), "=f"(r1c0) : "l"(h01[0]));
    asm("mov.b64 {%0, %1}, %2;" : "=f"(r2c0), "=f"(r3c0) : "l"(h23[0]));
    asm("mov.b64 {%0, %1}, %2;" : "=f"(r0c1), "=f"(r1c1) : "l"(h01[1]));
    asm("mov.b64 {%0, %1}, %2;" : "=f"(r2c1), "=f"(r3c1) : "l"(h23[1]));
    float rr[4][2] = {{r0c0, r0c1}, {r1c0, r1c1}, {r2c0, r2c1}, {r3c0, r3c1}};
#pragma unroll
    for (int i = 0; i < 4; i++) {
        int r = row0 + tr * 4 + i;
        if (r < M) {
            float2 v = make_float2(fmaxf(rr[i][0] + b20, 0.f), fmaxf(rr[i][1] + b21, 0.f));
            *reinterpret_cast<float2*>(H2 + (size_t)r * DM + tc * 2) = v;
        }
    }
}

// ---------------- BN stats ----------------
template<int N>
__global__ void bn_stats_kernel(const float* __restrict__ H, int M,
                                double* __restrict__ sum, double* __restrict__ sq) {
    int f = threadIdx.x;
    double s = 0.0, s2 = 0.0;
    for (int i = blockIdx.x; i < M; i += gridDim.x) {
        double v = (double)H[(size_t)i * N + f];
        s += v;
        s2 += v * v;
    }
    atomicAdd(&sum[f], s);
    atomicAdd(&sq[f], s2);
}

// ---------------- BN affine params: a = g*rs, c = b - m*a ----------------
__global__ void bnparam_kernel(const double* __restrict__ sum, const double* __restrict__ sq,
                               const float* __restrict__ g, const float* __restrict__ b,
                               float* __restrict__ a, float* __restrict__ c, int N, int M) {
    int t = threadIdx.x;
    if (t >= N) return;
    double m = sum[t] / (double)M;
    double var = sq[t] / (double)M - m * m;
    float rs = rsqrtf((float)var + BN_EPS);
    float af = g[t] * rs;
    a[t] = af;
    c[t] = b[t] - (float)m * af;
}

// ---------------- raw pool + counts ----------------
__global__ void pool_kernel(const float* __restrict__ H2, const int* __restrict__ batch, int M) {
    int idx = blockIdx.x * blockDim.x + threadIdx.x;
    if (idx >= M * DM) return;
    int i = idx / DM;
    int f = idx % DM;
    int b = __ldg(&batch[i]);
    atomicAdd(&g_pool[b * DM + f], H2[idx]);
    if (f == 0) atomicAdd(&g_cnt[b], 1);
}

// ---------------- dense head (applies BN2 affine to raw pool) ----------------
__global__ void head_kernel(const float* __restrict__ fcxd_w, const float* __restrict__ fcxd_b,
                            const float* __restrict__ fc1_w,  const float* __restrict__ fc1_b,
                            const float* __restrict__ fc2_w,  const float* __restrict__ fc2_b,
                            const float* __restrict__ fc3_w,  const float* __restrict__ fc3_b,
                            const float* __restrict__ fc4_w,  const float* __restrict__ fc4_b,
                            const float* __restrict__ fc5_w,  const float* __restrict__ fc5_b,
                            float* __restrict__ out) {
    __shared__ float p[DM], z1[64], z2[32], z3[16], z4[8], z5[2];
    int g = blockIdx.x, t = threadIdx.x;
    if (t < DM) {
        float cnt = (float)g_cnt[g];
        p[t] = g_a2[t] * g_pool[g * DM + t] + cnt * g_c2[t];
    }
    __syncthreads();
    if (t < 64) {
        float s = fcxd_b[t];
        for (int k = 0; k < 32; k++) s += p[k] * fcxd_w[k * 64 + t];
        z1[t] = fmaxf(s, 0.0f);
    }
    __syncthreads();
    if (t < 32) {
        float s = fc1_b[t];
        for (int k = 0; k < 64; k++) s += z1[k] * fc1_w[k * 32 + t];
        z2[t] = s;
    }
    __syncthreads();
    if (t < 16) {
        float s = fc2_b[t];
        for (int k = 0; k < 32; k++) s += z2[k] * fc2_w[k * 16 + t];
        z3[t] = s;
    }
    __syncthreads();
    if (t < 8) {
        float s = fc3_b[t];
        for (int k = 0; k < 16; k++) s += z3[k] * fc3_w[k * 8 + t];
        z4[t] = s;
    }
    __syncthreads();
    if (t < 2) {
        float s = fc4_b[t];
        for (int k = 0; k < 8; k++) s += z4[k] * fc4_w[k * 2 + t];
        z5[t] = s;
    }
    __syncthreads();
    if (t == 0) out[g] = z5[0] * fc5_w[0] + z5[1] * fc5_w[1] + fc5_b[0];
}

// ---------------- launch ----------------
extern "C" void kernel_launch(void* const* d_in, const int* in_sizes, int n_in,
                              void* d_out, int out_size) {
    const float* x      = (const float*)d_in[0];
    const int*   src    = (const int*)d_in[1];
    const int*   dst    = (const int*)d_in[2];
    const int*   batch  = (const int*)d_in[3];
    const float* g1_w1  = (const float*)d_in[4];
    const float* g1_b1  = (const float*)d_in[5];
    const float* g1_w2  = (const float*)d_in[6];
    const float* g1_b2  = (const float*)d_in[7];
    const float* bn1_g  = (const float*)d_in[8];
    const float* bn1_b  = (const float*)d_in[9];
    const float* g2_w1  = (const float*)d_in[10];
    const float* g2_b1  = (const float*)d_in[11];
    const float* g2_w2  = (const float*)d_in[12];
    const float* g2_b2  = (const float*)d_in[13];
    const float* bn2_g  = (const float*)d_in[14];
    const float* bn2_b  = (const float*)d_in[15];
    const float* fcxd_w = (const float*)d_in[16];
    const float* fcxd_b = (const float*)d_in[17];
    const float* fc1_w  = (const float*)d_in[18];
    const float* fc1_b  = (const float*)d_in[19];
    const float* fc2_w  = (const float*)d_in[20];
    const float* fc2_b  = (const float*)d_in[21];
    const float* fc3_w  = (const float*)d_in[22];
    const float* fc3_b  = (const float*)d_in[23];
    const float* fc4_w  = (const float*)d_in[24];
    const float* fc4_b  = (const float*)d_in[25];
    const float* fc5_w  = (const float*)d_in[26];
    const float* fc5_b  = (const float*)d_in[27];
    float* out = (float*)d_out;

    const int E = in_sizes[1];
    const int M = NN;

    float *A, *T, *H, *B, *H2, *a1, *c1, *a2, *c2;
    double *sum1, *sq1, *sum2, *sq2;
    cudaGetSymbolAddress((void**)&A,  g_A);
    cudaGetSymbolAddress((void**)&T,  g_T);
    cudaGetSymbolAddress((void**)&H,  g_H);
    cudaGetSymbolAddress((void**)&B,  g_B);
    cudaGetSymbolAddress((void**)&H2, g_H2);
    cudaGetSymbolAddress((void**)&a1, g_a1);
    cudaGetSymbolAddress((void**)&c1, g_c1);
    cudaGetSymbolAddress((void**)&a2, g_a2);
    cudaGetSymbolAddress((void**)&c2, g_c2);
    cudaGetSymbolAddress((void**)&sum1, g_sum1);
    cudaGetSymbolAddress((void**)&sq1,  g_sq1);
    cudaGetSymbolAddress((void**)&sum2, g_sum2);
    cudaGetSymbolAddress((void**)&sq2,  g_sq2);

    // CSR build (also zeroes stats/pool)
    zero_kernel<<<(NN + 255) / 256, 256>>>();
    hist_kernel<<<(E + 255) / 256, 256>>>(dst, E);
    scan_kernel<<<1, 1024>>>();
    fill_kernel<<<(E + 255) / 256, 256>>>(src, dst, E);

    // ---- GIN layer 1 ----
    agg_kernel<0><<<(NN + 7) / 8, 256>>>(x, A, nullptr, nullptr);
    gemm112_kernel<<<(M + 63) / 64, 256>>>(A, g1_w1, g1_b1, T, M);
    gemm112_kernel<<<(M + 63) / 64, 256>>>(T, g1_w2, g1_b2, H, M);
    bn_stats_kernel<FI><<<512, FI>>>(H, M, sum1, sq1);
    bnparam_kernel<<<1, FI>>>(sum1, sq1, bn1_g, bn1_b, a1, c1, FI, M);

    // ---- GIN layer 2 (BN1 affine folded into aggregation) ----
    agg_kernel<1><<<(NN + 7) / 8, 256>>>(H, B, a1, c1);
    mlp2_kernel<<<(M + 63) / 64, 256>>>(B, g2_w1, g2_b1, g2_w2, g2_b2, H2, M);
    bn_stats_kernel<DM><<<512, DM>>>(H2, M, sum2, sq2);
    bnparam_kernel<<<1, DM>>>(sum2, sq2, bn2_g, bn2_b, a2, c2, DM, M);

    // ---- pool (raw) + head (applies BN2 affine) ----
    pool_kernel<<<(M * DM + 255) / 256, 256>>>(H2, batch, M);
    head_kernel<<<NG, 64>>>(fcxd_w, fcxd_b, fc1_w, fc1_b, fc2_w, fc2_b,
                            fc3_w, fc3_b, fc4_w, fc4_b, fc5_w, fc5_b, out);
}

// round 4
// speedup vs baseline: 2.5824x; 1.3254x over previous
#include <cuda_runtime.h>
#include <cuda_bf16.h>
#include <cstdint>

#define NN 50000
#define NE 800000
#define FI 112
#define DM 32
#define NG 256
#define BN_EPS 1e-5f

typedef unsigned long long u64;

// ---------------- device scratch ----------------
__device__ float  g_A [NN * FI];   // Y1 = x @ W11
__device__ float  g_T [NN * FI];   // T  = relu(Y1 + aggY1 + b1)
__device__ float  g_H [NN * FI];   // H  = relu(T @ W12 + b2)
__device__ float  g_Y2[NN * DM];   // Y2 = (a1*H) @ W21
__device__ float  g_Z [NN * DM];   // Z  = relu(Y2 + aggY2 + (1+deg)K2C + b21)
__device__ double g_sum1[FI], g_sq1[FI];
__device__ double g_sum2[DM], g_sq2[DM];
__device__ float  g_a1[FI], g_c1[FI];
__device__ float  g_a2[DM], g_c2[DM];
__device__ float  g_k2c[DM];
__device__ float  g_pool[NG * DM];
__device__ int    g_cnt[NG];
__device__ int    g_deg[NN];
__device__ int    g_rowptr[NN + 1];
__device__ int    g_cursor[NN];
__device__ int    g_col[NE];

// ---------------- zero ----------------
__global__ void zero_kernel() {
    int t = blockIdx.x * blockDim.x + threadIdx.x;
    if (t < NN) g_deg[t] = 0;
    if (t < FI) { g_sum1[t] = 0.0; g_sq1[t] = 0.0; }
    if (t < DM) { g_sum2[t] = 0.0; g_sq2[t] = 0.0; }
    if (t < NG * DM) g_pool[t] = 0.0f;
    if (t < NG) g_cnt[t] = 0;
}

// ---------------- CSR build ----------------
__global__ void hist_kernel(const int* __restrict__ dst, int E) {
    int e = blockIdx.x * blockDim.x + threadIdx.x;
    if (e < E) atomicAdd(&g_deg[dst[e]], 1);
}

__global__ void scan_kernel() {
    const int CH = (NN + 1023) >> 10;
    int t = threadIdx.x;
    int base = t * CH;
    int s = 0;
    for (int i = 0; i < CH; i++) {
        int idx = base + i;
        if (idx < NN) s += g_deg[idx];
    }
    int lane = t & 31, wid = t >> 5;
    int v = s;
#pragma unroll
    for (int d = 1; d < 32; d <<= 1) {
        int n = __shfl_up_sync(0xffffffffu, v, d);
        if (lane >= d) v += n;
    }
    __shared__ int wsum[32];
    if (lane == 31) wsum[wid] = v;
    __syncthreads();
    if (wid == 0) {
        int w = wsum[lane];
#pragma unroll
        for (int d = 1; d < 32; d <<= 1) {
            int n = __shfl_up_sync(0xffffffffu, w, d);
            if (lane >= d) w += n;
        }
        wsum[lane] = w;
    }
    __syncthreads();
    int excl = v - s + (wid ? wsum[wid - 1] : 0);
    int run = excl;
    for (int i = 0; i < CH; i++) {
        int idx = base + i;
        if (idx < NN) {
            g_rowptr[idx] = run;
            g_cursor[idx] = run;
            run += g_deg[idx];
        }
    }
    if (t == 1023) g_rowptr[NN] = excl;
}

__global__ void fill_kernel(const int* __restrict__ src, const int* __restrict__ dst, int E) {
    int e = blockIdx.x * blockDim.x + threadIdx.x;
    if (e < E) {
        int p = atomicAdd(&g_cursor[dst[e]], 1);
        g_col[p] = src[e];
    }
}

// ---------------- agg112: out = relu(Y_i + sum_j Y_j + b1), warp/node, float4 ----------------
__global__ __launch_bounds__(256) void agg112_kernel(const float* __restrict__ Y,
                                                     const float* __restrict__ b1,
                                                     float* __restrict__ out) {
    int node = blockIdx.x * 8 + (threadIdx.x >> 5);
    if (node >= NN) return;
    int lane = threadIdx.x & 31;
    int beg = __ldg(&g_rowptr[node]);
    int end = __ldg(&g_rowptr[node + 1]);
    bool act = lane < 28;
    size_t foff = (size_t)(lane << 2);

    float4 acc  = make_float4(0.f, 0.f, 0.f, 0.f);
    float4 acc1 = acc, acc2 = acc, acc3 = acc;
    if (act) acc = *reinterpret_cast<const float4*>(Y + (size_t)node * FI + foff);

    int e = beg;
    for (; e + 4 <= end; e += 4) {
        int s0 = __ldg(&g_col[e + 0]);
        int s1 = __ldg(&g_col[e + 1]);
        int s2 = __ldg(&g_col[e + 2]);
        int s3 = __ldg(&g_col[e + 3]);
        if (act) {
            float4 v0 = *reinterpret_cast<const float4*>(Y + (size_t)s0 * FI + foff);
            float4 v1 = *reinterpret_cast<const float4*>(Y + (size_t)s1 * FI + foff);
            float4 v2 = *reinterpret_cast<const float4*>(Y + (size_t)s2 * FI + foff);
            float4 v3 = *reinterpret_cast<const float4*>(Y + (size_t)s3 * FI + foff);
            acc.x += v0.x; acc.y += v0.y; acc.z += v0.z; acc.w += v0.w;
            acc1.x += v1.x; acc1.y += v1.y; acc1.z += v1.z; acc1.w += v1.w;
            acc2.x += v2.x; acc2.y += v2.y; acc2.z += v2.z; acc2.w += v2.w;
            acc3.x += v3.x; acc3.y += v3.y; acc3.z += v3.z; acc3.w += v3.w;
        }
    }
    for (; e < end; e++) {
        int s = __ldg(&g_col[e]);
        if (act) {
            float4 v = *reinterpret_cast<const float4*>(Y + (size_t)s * FI + foff);
            acc.x += v.x; acc.y += v.y; acc.z += v.z; acc.w += v.w;
        }
    }
    if (!act) return;
    float4 b = *reinterpret_cast<const float4*>(b1 + foff);
    float4 r;
    r.x = fmaxf((acc.x + acc1.x) + (acc2.x + acc3.x) + b.x, 0.f);
    r.y = fmaxf((acc.y + acc1.y) + (acc2.y + acc3.y) + b.y, 0.f);
    r.z = fmaxf((acc.z + acc1.z) + (acc2.z + acc3.z) + b.z, 0.f);
    r.w = fmaxf((acc.w + acc1.w) + (acc2.w + acc3.w) + b.w, 0.f);
    *reinterpret_cast<float4*>(out + (size_t)node * FI + foff) = r;
}

// ---------------- agg32: Z = relu(Y2_i + sum_j Y2_j + (1+deg)*K2C + b21), warp/node scalar ----------------
__global__ __launch_bounds__(256) void agg32_kernel(const float* __restrict__ Y2,
                                                    const float* __restrict__ b21,
                                                    float* __restrict__ Z) {
    int node = blockIdx.x * 8 + (threadIdx.x >> 5);
    if (node >= NN) return;
    int lane = threadIdx.x & 31;
    int beg = __ldg(&g_rowptr[node]);
    int end = __ldg(&g_rowptr[node + 1]);

    float acc = Y2[(size_t)node * DM + lane];
    float a1v = 0.f, a2v = 0.f, a3v = 0.f;
    int e = beg;
    for (; e + 4 <= end; e += 4) {
        int s0 = __ldg(&g_col[e + 0]);
        int s1 = __ldg(&g_col[e + 1]);
        int s2 = __ldg(&g_col[e + 2]);
        int s3 = __ldg(&g_col[e + 3]);
        acc += Y2[(size_t)s0 * DM + lane];
        a1v += Y2[(size_t)s1 * DM + lane];
        a2v += Y2[(size_t)s2 * DM + lane];
        a3v += Y2[(size_t)s3 * DM + lane];
    }
    for (; e < end; e++) acc += Y2[(size_t)__ldg(&g_col[e]) * DM + lane];
    float dp1 = (float)(1 + end - beg);
    float z = (acc + a1v) + (a2v + a3v) + dp1 * g_k2c[lane] + __ldg(&b21[lane]);
    Z[(size_t)node * DM + lane] = fmaxf(z, 0.f);
}

// ---------------- 112x112 GEMM: 128-row tiles, 8 rows x 7 cols / thread, f32x2 ----------------
template<int BIAS_RELU, int STATS>
__global__ __launch_bounds__(256) void gemm112_kernel(const float* __restrict__ A,
                                                      const float* __restrict__ W,
                                                      const float* __restrict__ bias,
                                                      float* __restrict__ C, int M) {
    __shared__ __align__(16) float  As[16][132];
    __shared__ __align__(16) float2 Wd[16][112];
    const int tid = threadIdx.x;
    const int tr = tid >> 4;   // rows tr*8 .. +7
    const int tc = tid & 15;   // cols tc*7 .. +6
    const int row0 = blockIdx.x * 128;

    u64 acc01[7], acc23[7], acc45[7], acc67[7];
#pragma unroll
    for (int j = 0; j < 7; j++) { acc01[j] = 0ull; acc23[j] = 0ull; acc45[j] = 0ull; acc67[j] = 0ull; }

    for (int kc = 0; kc < 112; kc += 16) {
#pragma unroll
        for (int i = 0; i < 2; i++) {
            int idx = tid + i * 256;
            int r = idx >> 2;
            int kq = (idx & 3) << 2;
            float4 v = make_float4(0.f, 0.f, 0.f, 0.f);
            if (row0 + r < M)
                v = *reinterpret_cast<const float4*>(A + (size_t)(row0 + r) * 112 + kc + kq);
            As[kq + 0][r] = v.x;
            As[kq + 1][r] = v.y;
            As[kq + 2][r] = v.z;
            As[kq + 3][r] = v.w;
        }
#pragma unroll
        for (int i = 0; i < 7; i++) {
            int idx = tid + i * 256;
            int c = idx % 112, kk = idx / 112;
            float w = W[(size_t)(kc + kk) * 112 + c];
            Wd[kk][c] = make_float2(w, w);
        }
        __syncthreads();
#pragma unroll
        for (int kk = 0; kk < 16; kk++) {
            float4 alo = *reinterpret_cast<const float4*>(&As[kk][tr * 8]);
            float4 ahi = *reinterpret_cast<const float4*>(&As[kk][tr * 8 + 4]);
            u64 a01, a23, a45, a67;
            asm("mov.b64 %0, {%1, %2};" : "=l"(a01) : "f"(alo.x), "f"(alo.y));
            asm("mov.b64 %0, {%1, %2};" : "=l"(a23) : "f"(alo.z), "f"(alo.w));
            asm("mov.b64 %0, {%1, %2};" : "=l"(a45) : "f"(ahi.x), "f"(ahi.y));
            asm("mov.b64 %0, {%1, %2};" : "=l"(a67) : "f"(ahi.z), "f"(ahi.w));
#pragma unroll
            for (int j = 0; j < 7; j++) {
                u64 wp = *reinterpret_cast<const u64*>(&Wd[kk][tc * 7 + j]);
                asm("fma.rn.f32x2 %0, %1, %2, %0;" : "+l"(acc01[j]) : "l"(a01), "l"(wp));
                asm("fma.rn.f32x2 %0, %1, %2, %0;" : "+l"(acc23[j]) : "l"(a23), "l"(wp));
                asm("fma.rn.f32x2 %0, %1, %2, %0;" : "+l"(acc45[j]) : "l"(a45), "l"(wp));
                asm("fma.rn.f32x2 %0, %1, %2, %0;" : "+l"(acc67[j]) : "l"(a67), "l"(wp));
            }
        }
        __syncthreads();
    }

    const int r0 = row0 + tr * 8;
    float s[7], q[7];
#pragma unroll
    for (int j = 0; j < 7; j++) {
        int c = tc * 7 + j;
        float b = BIAS_RELU ? __ldg(&bias[c]) : 0.f;
        float v[8];
        asm("mov.b64 {%0, %1}, %2;" : "=f"(v[0]), "=f"(v[1]) : "l"(acc01[j]));
        asm("mov.b64 {%0, %1}, %2;" : "=f"(v[2]), "=f"(v[3]) : "l"(acc23[j]));
        asm("mov.b64 {%0, %1}, %2;" : "=f"(v[4]), "=f"(v[5]) : "l"(acc45[j]));
        asm("mov.b64 {%0, %1}, %2;" : "=f"(v[6]), "=f"(v[7]) : "l"(acc67[j]));
        float ss = 0.f, qq = 0.f;
#pragma unroll
        for (int i = 0; i < 8; i++) {
            float o = BIAS_RELU ? fmaxf(v[i] + b, 0.f) : v[i];
            if (r0 + i < M) {
                C[(size_t)(r0 + i) * 112 + c] = o;
                ss += o;
                qq += o * o;
            }
        }
        s[j] = ss; q[j] = qq;
    }

    if (STATS) {
        __syncthreads();
#pragma unroll
        for (int j = 0; j < 7; j++)
            Wd[tr][tc * 7 + j] = make_float2(s[j], q[j]);
        __syncthreads();
        if (tid < 112) {
            float S = 0.f, Q = 0.f;
#pragma unroll
            for (int t = 0; t < 16; t++) {
                float2 p = Wd[t][tid];
                S += p.x; Q += p.y;
            }
            atomicAdd(&g_sum1[tid], (double)S);
            atomicAdd(&g_sq1[tid],  (double)Q);
        }
    }
}

// ---------------- gemmY2: Y2 = (a1 * H) @ W21, 64-row tiles, 4x2 / thread ----------------
#define SWZ(k, r) (((((r) >> 2) ^ ((k) & 15)) << 2) | ((r) & 3))
__global__ __launch_bounds__(256) void gemmY2_kernel(const float* __restrict__ H,
                                                     const float* __restrict__ W21,
                                                     float* __restrict__ Y2, int M) {
    __shared__ __align__(16) float Bs[112 * 64];
    __shared__ __align__(16) float W1s[112][32];
    const int tid = threadIdx.x;
    const int tr = tid >> 4;
    const int tc = tid & 15;
    const int row0 = blockIdx.x * 64;

    for (int idx = tid; idx < 112 * 32; idx += 256) W1s[idx >> 5][idx & 31] = W21[idx];
    for (int idx = tid; idx < 64 * 112; idx += 256) {
        int k = idx % 112, r = idx / 112;
        float v = (row0 + r < M) ? H[(size_t)(row0 + r) * 112 + k] * __ldg(&g_a1[k]) : 0.f;
        Bs[k * 64 + SWZ(k, r)] = v;
    }
    __syncthreads();

    u64 z01[2], z23[2];
#pragma unroll
    for (int j = 0; j < 2; j++) { z01[j] = 0ull; z23[j] = 0ull; }
    for (int k = 0; k < 112; k++) {
        int grp = (tr ^ (k & 15)) << 2;
        float4 av = *reinterpret_cast<const float4*>(&Bs[k * 64 + grp]);
        u64 a01, a23;
        asm("mov.b64 %0, {%1, %2};" : "=l"(a01) : "f"(av.x), "f"(av.y));
        asm("mov.b64 %0, {%1, %2};" : "=l"(a23) : "f"(av.z), "f"(av.w));
        float2 w = *reinterpret_cast<const float2*>(&W1s[k][tc * 2]);
        u64 w0, w1;
        asm("mov.b64 %0, {%1, %1};" : "=l"(w0) : "f"(w.x));
        asm("mov.b64 %0, {%1, %1};" : "=l"(w1) : "f"(w.y));
        asm("fma.rn.f32x2 %0, %1, %2, %0;" : "+l"(z01[0]) : "l"(a01), "l"(w0));
        asm("fma.rn.f32x2 %0, %1, %2, %0;" : "+l"(z23[0]) : "l"(a23), "l"(w0));
        asm("fma.rn.f32x2 %0, %1, %2, %0;" : "+l"(z01[1]) : "l"(a01), "l"(w1));
        asm("fma.rn.f32x2 %0, %1, %2, %0;" : "+l"(z23[1]) : "l"(a23), "l"(w1));
    }
    float v0, v1, v2, v3, u0, u1, u2, u3;
    asm("mov.b64 {%0, %1}, %2;" : "=f"(v0), "=f"(v1) : "l"(z01[0]));
    asm("mov.b64 {%0, %1}, %2;" : "=f"(v2), "=f"(v3) : "l"(z23[0]));
    asm("mov.b64 {%0, %1}, %2;" : "=f"(u0), "=f"(u1) : "l"(z01[1]));
    asm("mov.b64 {%0, %1}, %2;" : "=f"(u2), "=f"(u3) : "l"(z23[1]));
    float rr[4][2] = {{v0, u0}, {v1, u1}, {v2, u2}, {v3, u3}};
#pragma unroll
    for (int i = 0; i < 4; i++) {
        int r = row0 + tr * 4 + i;
        if (r < M)
            *reinterpret_cast<float2*>(Y2 + (size_t)r * DM + tc * 2) = make_float2(rr[i][0], rr[i][1]);
    }
}

// ---------------- gemm32: H2 = relu(Z @ W22 + b22) fused stats2 + pool + cnt ----------------
__global__ __launch_bounds__(256) void gemm32_kernel(const float* __restrict__ Z,
                                                     const float* __restrict__ W22,
                                                     const float* __restrict__ b22,
                                                     const int* __restrict__ batch, int M) {
    __shared__ __align__(16) float Zs[32 * 64];
    __shared__ __align__(16) float W2s[32][32];
    const int tid = threadIdx.x;
    const int tr = tid >> 4;
    const int tc = tid & 15;
    const int row0 = blockIdx.x * 64;

    for (int idx = tid; idx < 32 * 32; idx += 256) W2s[idx >> 5][idx & 31] = W22[idx];
    for (int idx = tid; idx < 64 * 32; idx += 256) {
        int k = idx % 32, r = idx / 32;
        float v = (row0 + r < M) ? Z[(size_t)(row0 + r) * 32 + k] : 0.f;
        Zs[k * 64 + SWZ(k, r)] = v;
    }
    __syncthreads();

    u64 h01[2], h23[2];
#pragma unroll
    for (int j = 0; j < 2; j++) { h01[j] = 0ull; h23[j] = 0ull; }
#pragma unroll
    for (int k = 0; k < 32; k++) {
        int grp = (tr ^ (k & 15)) << 2;
        float4 av = *reinterpret_cast<const float4*>(&Zs[k * 64 + grp]);
        u64 a01, a23;
        asm("mov.b64 %0, {%1, %2};" : "=l"(a01) : "f"(av.x), "f"(av.y));
        asm("mov.b64 %0, {%1, %2};" : "=l"(a23) : "f"(av.z), "f"(av.w));
        float2 w = *reinterpret_cast<const float2*>(&W2s[k][tc * 2]);
        u64 w0, w1;
        asm("mov.b64 %0, {%1, %1};" : "=l"(w0) : "f"(w.x));
        asm("mov.b64 %0, {%1, %1};" : "=l"(w1) : "f"(w.y));
        asm("fma.rn.f32x2 %0, %1, %2, %0;" : "+l"(h01[0]) : "l"(a01), "l"(w0));
        asm("fma.rn.f32x2 %0, %1, %2, %0;" : "+l"(h23[0]) : "l"(a23), "l"(w0));
        asm("fma.rn.f32x2 %0, %1, %2, %0;" : "+l"(h01[1]) : "l"(a01), "l"(w1));
        asm("fma.rn.f32x2 %0, %1, %2, %0;" : "+l"(h23[1]) : "l"(a23), "l"(w1));
    }

    float b0 = __ldg(&b22[tc * 2]);
    float b1 = __ldg(&b22[tc * 2 + 1]);
    float v0, v1, v2, v3, u0, u1, u2, u3;
    asm("mov.b64 {%0, %1}, %2;" : "=f"(v0), "=f"(v1) : "l"(h01[0]));
    asm("mov.b64 {%0, %1}, %2;" : "=f"(v2), "=f"(v3) : "l"(h23[0]));
    asm("mov.b64 {%0, %1}, %2;" : "=f"(u0), "=f"(u1) : "l"(h01[1]));
    asm("mov.b64 {%0, %1}, %2;" : "=f"(u2), "=f"(u3) : "l"(h23[1]));
    float rr[4][2] = {{v0, u0}, {v1, u1}, {v2, u2}, {v3, u3}};

    float s0 = 0.f, q0 = 0.f, s1 = 0.f, q1 = 0.f;
#pragma unroll
    for (int i = 0; i < 4; i++) {
        int r = row0 + tr * 4 + i;
        float o0 = fmaxf(rr[i][0] + b0, 0.f);
        float o1 = fmaxf(rr[i][1] + b1, 0.f);
        rr[i][0] = o0; rr[i][1] = o1;
        if (r < M) {
            s0 += o0; q0 += o0 * o0;
            s1 += o1; q1 += o1 * o1;
        }
    }

    // stats reduction (reuse Zs)
    __syncthreads();
    float2* part = reinterpret_cast<float2*>(Zs);
    part[tr * 32 + tc * 2]     = make_float2(s0, q0);
    part[tr * 32 + tc * 2 + 1] = make_float2(s1, q1);
    __syncthreads();
    if (tid < 32) {
        float S = 0.f, Q = 0.f;
#pragma unroll
        for (int t = 0; t < 16; t++) {
            float2 p = part[t * 32 + tid];
            S += p.x; Q += p.y;
        }
        atomicAdd(&g_sum2[tid], (double)S);
        atomicAdd(&g_sq2[tid],  (double)Q);
    }

    // pool + counts (raw sums; BN2 affine applied in head)
#pragma unroll
    for (int i = 0; i < 4; i++) {
        int r = row0 + tr * 4 + i;
        if (r < M) {
            int b = __ldg(&batch[r]);
            atomicAdd(&g_pool[b * DM + tc * 2],     rr[i][0]);
            atomicAdd(&g_pool[b * DM + tc * 2 + 1], rr[i][1]);
            if (tc == 0) atomicAdd(&g_cnt[b], 1);
        }
    }
}

// ---------------- bnparam1: a1,c1 and K2C = c1^T @ W21 ----------------
__global__ void bnparam1_kernel(const float* __restrict__ g, const float* __restrict__ b,
                                const float* __restrict__ W21, int M) {
    __shared__ float c1s[FI];
    int t = threadIdx.x;
    if (t < FI) {
        double m = g_sum1[t] / (double)M;
        double var = g_sq1[t] / (double)M - m * m;
        float rs = rsqrtf((float)var + BN_EPS);
        float af = g[t] * rs;
        float cf = b[t] - (float)m * af;
        g_a1[t] = af;
        g_c1[t] = cf;
        c1s[t] = cf;
    }
    __syncthreads();
    if (t < DM) {
        float s = 0.f;
        for (int k = 0; k < FI; k++) s += c1s[k] * W21[k * DM + t];
        g_k2c[t] = s;
    }
}

// ---------------- bnparam2 ----------------
__global__ void bnparam2_kernel(const float* __restrict__ g, const float* __restrict__ b, int M) {
    int t = threadIdx.x;
    if (t >= DM) return;
    double m = g_sum2[t] / (double)M;
    double var = g_sq2[t] / (double)M - m * m;
    float rs = rsqrtf((float)var + BN_EPS);
    float af = g[t] * rs;
    g_a2[t] = af;
    g_c2[t] = b[t] - (float)m * af;
}

// ---------------- dense head (applies BN2 affine to raw pool) ----------------
__global__ void head_kernel(const float* __restrict__ fcxd_w, const float* __restrict__ fcxd_b,
                            const float* __restrict__ fc1_w,  const float* __restrict__ fc1_b,
                            const float* __restrict__ fc2_w,  const float* __restrict__ fc2_b,
                            const float* __restrict__ fc3_w,  const float* __restrict__ fc3_b,
                            const float* __restrict__ fc4_w,  const float* __restrict__ fc4_b,
                            const float* __restrict__ fc5_w,  const float* __restrict__ fc5_b,
                            float* __restrict__ out) {
    __shared__ float p[DM], z1[64], z2[32], z3[16], z4[8], z5[2];
    int g = blockIdx.x, t = threadIdx.x;
    if (t < DM) {
        float cnt = (float)g_cnt[g];
        p[t] = g_a2[t] * g_pool[g * DM + t] + cnt * g_c2[t];
    }
    __syncthreads();
    if (t < 64) {
        float s = fcxd_b[t];
        for (int k = 0; k < 32; k++) s += p[k] * fcxd_w[k * 64 + t];
        z1[t] = fmaxf(s, 0.0f);
    }
    __syncthreads();
    if (t < 32) {
        float s = fc1_b[t];
        for (int k = 0; k < 64; k++) s += z1[k] * fc1_w[k * 32 + t];
        z2[t] = s;
    }
    __syncthreads();
    if (t < 16) {
        float s = fc2_b[t];
        for (int k = 0; k < 32; k++) s += z2[k] * fc2_w[k * 16 + t];
        z3[t] = s;
    }
    __syncthreads();
    if (t < 8) {
        float s = fc3_b[t];
        for (int k = 0; k < 16; k++) s += z3[k] * fc3_w[k * 8 + t];
        z4[t] = s;
    }
    __syncthreads();
    if (t < 2) {
        float s = fc4_b[t];
        for (int k = 0; k < 8; k++) s += z4[k] * fc4_w[k * 2 + t];
        z5[t] = s;
    }
    __syncthreads();
    if (t == 0) out[g] = z5[0] * fc5_w[0] + z5[1] * fc5_w[1] + fc5_b[0];
}

// ---------------- launch ----------------
extern "C" void kernel_launch(void* const* d_in, const int* in_sizes, int n_in,
                              void* d_out, int out_size) {
    const float* x      = (const float*)d_in[0];
    const int*   src    = (const int*)d_in[1];
    const int*   dst    = (const int*)d_in[2];
    const int*   batch  = (const int*)d_in[3];
    const float* g1_w1  = (const float*)d_in[4];
    const float* g1_b1  = (const float*)d_in[5];
    const float* g1_w2  = (const float*)d_in[6];
    const float* g1_b2  = (const float*)d_in[7];
    const float* bn1_g  = (const float*)d_in[8];
    const float* bn1_b  = (const float*)d_in[9];
    const float* g2_w1  = (const float*)d_in[10];
    const float* g2_b1  = (const float*)d_in[11];
    const float* g2_w2  = (const float*)d_in[12];
    const float* g2_b2  = (const float*)d_in[13];
    const float* bn2_g  = (const float*)d_in[14];
    const float* bn2_b  = (const float*)d_in[15];
    const float* fcxd_w = (const float*)d_in[16];
    const float* fcxd_b = (const float*)d_in[17];
    const float* fc1_w  = (const float*)d_in[18];
    const float* fc1_b  = (const float*)d_in[19];
    const float* fc2_w  = (const float*)d_in[20];
    const float* fc2_b  = (const float*)d_in[21];
    const float* fc3_w  = (const float*)d_in[22];
    const float* fc3_b  = (const float*)d_in[23];
    const float* fc4_w  = (const float*)d_in[24];
    const float* fc4_b  = (const float*)d_in[25];
    const float* fc5_w  = (const float*)d_in[26];
    const float* fc5_b  = (const float*)d_in[27];
    float* out = (float*)d_out;

    const int E = in_sizes[1];
    const int M = NN;

    float *Y1, *T, *H, *Y2, *Z;
    cudaGetSymbolAddress((void**)&Y1, g_A);
    cudaGetSymbolAddress((void**)&T,  g_T);
    cudaGetSymbolAddress((void**)&H,  g_H);
    cudaGetSymbolAddress((void**)&Y2, g_Y2);
    cudaGetSymbolAddress((void**)&Z,  g_Z);

    // zero + CSR build
    zero_kernel<<<(NN + 255) / 256, 256>>>();
    hist_kernel<<<(E + 255) / 256, 256>>>(dst, E);
    scan_kernel<<<1, 1024>>>();
    fill_kernel<<<(E + 255) / 256, 256>>>(src, dst, E);

    // ---- GIN layer 1 (GEMM-first; agg(X)@W == agg(X@W)) ----
    gemm112_kernel<0, 0><<<(M + 127) / 128, 256>>>(x, g1_w1, nullptr, Y1, M);      // Y1 = x @ W11
    agg112_kernel<<<(NN + 7) / 8, 256>>>(Y1, g1_b1, T);                            // T = relu(Y1+agg+b1)
    gemm112_kernel<1, 1><<<(M + 127) / 128, 256>>>(T, g1_w2, g1_b2, H, M);         // H = relu(T@W12+b2), +stats1
    bnparam1_kernel<<<1, 128>>>(bn1_g, bn1_b, g2_w1, M);                           // a1,c1,K2C

    // ---- GIN layer 2 (32-wide aggregation) ----
    gemmY2_kernel<<<(M + 63) / 64, 256>>>(H, g2_w1, Y2, M);                        // Y2 = (a1*H)@W21
    agg32_kernel<<<(NN + 7) / 8, 256>>>(Y2, g2_b1, Z);                             // Z = relu(Y2+agg+(1+deg)K2C+b21)
    gemm32_kernel<<<(M + 63) / 64, 256>>>(Z, g2_w2, g2_b2, batch, M);              // fused: relu GEMM + stats2 + pool + cnt
    bnparam2_kernel<<<1, DM>>>(bn2_g, bn2_b, M);

    // ---- head ----
    head_kernel<<<NG, 64>>>(fcxd_w, fcxd_b, fc1_w, fc1_b, fc2_w, fc2_b,
                            fc3_w, fc3_b, fc4_w, fc4_b, fc5_w, fc5_b, out);
}

// round 5
// speedup vs baseline: 2.6577x; 1.0291x over previous
#include <cuda_runtime.h>
#include <cuda_bf16.h>
#include <cstdint>

#define NN 50000
#define NE 800000
#define FI 112
#define DM 32
#define NG 256
#define BN_EPS 1e-5f

typedef unsigned long long u64;

// ---------------- device scratch ----------------
__device__ float  g_A [NN * FI];   // Y1 = x @ W11
__device__ float  g_T [NN * FI];   // T  = relu(Y1 + aggY1 + b1)
__device__ float  g_H [NN * FI];   // H  = relu(T @ W12 + b2)
__device__ float  g_Y2[NN * DM];   // Y2 = (a1*H) @ W21
__device__ float  g_Z [NN * DM];   // Z  = relu(Y2 + aggY2 + (1+deg)K2C + b21)
__device__ double g_sum1[FI], g_sq1[FI];
__device__ double g_sum2[DM], g_sq2[DM];
__device__ float  g_k2c[DM];
__device__ float  g_pool[NG * DM];
__device__ int    g_cnt[NG];
__device__ int    g_deg[NN];
__device__ int    g_rowptr[NN + 1];
__device__ int    g_cursor[NN];
__device__ int    g_col[NE];

// ---------------- zero ----------------
__global__ void zero_kernel() {
    int t = blockIdx.x * blockDim.x + threadIdx.x;
    if (t < NN) g_deg[t] = 0;
    if (t < FI) { g_sum1[t] = 0.0; g_sq1[t] = 0.0; }
    if (t < DM) { g_sum2[t] = 0.0; g_sq2[t] = 0.0; }
    if (t < NG * DM) g_pool[t] = 0.0f;
    if (t < NG) g_cnt[t] = 0;
}

// ---------------- CSR build (4 edges / thread for MLP) ----------------
__global__ void hist_kernel(const int* __restrict__ dst, int E) {
    int base = (blockIdx.x * blockDim.x + threadIdx.x) * 4;
    if (base + 4 <= E) {
        int4 d = *reinterpret_cast<const int4*>(dst + base);
        atomicAdd(&g_deg[d.x], 1);
        atomicAdd(&g_deg[d.y], 1);
        atomicAdd(&g_deg[d.z], 1);
        atomicAdd(&g_deg[d.w], 1);
    } else {
        for (int j = base; j < E; j++) atomicAdd(&g_deg[dst[j]], 1);
    }
}

__global__ void scan_kernel() {
    const int CH = (NN + 1023) >> 10;
    int t = threadIdx.x;
    int base = t * CH;
    int s = 0;
    for (int i = 0; i < CH; i++) {
        int idx = base + i;
        if (idx < NN) s += g_deg[idx];
    }
    int lane = t & 31, wid = t >> 5;
    int v = s;
#pragma unroll
    for (int d = 1; d < 32; d <<= 1) {
        int n = __shfl_up_sync(0xffffffffu, v, d);
        if (lane >= d) v += n;
    }
    __shared__ int wsum[32];
    if (lane == 31) wsum[wid] = v;
    __syncthreads();
    if (wid == 0) {
        int w = wsum[lane];
#pragma unroll
        for (int d = 1; d < 32; d <<= 1) {
            int n = __shfl_up_sync(0xffffffffu, w, d);
            if (lane >= d) w += n;
        }
        wsum[lane] = w;
    }
    __syncthreads();
    int excl = v - s + (wid ? wsum[wid - 1] : 0);
    int run = excl;
    for (int i = 0; i < CH; i++) {
        int idx = base + i;
        if (idx < NN) {
            g_rowptr[idx] = run;
            g_cursor[idx] = run;
            run += g_deg[idx];
        }
    }
    if (t == 1023) g_rowptr[NN] = excl;
}

__global__ void fill_kernel(const int* __restrict__ src, const int* __restrict__ dst, int E) {
    int base = (blockIdx.x * blockDim.x + threadIdx.x) * 4;
    if (base + 4 <= E) {
        int4 d = *reinterpret_cast<const int4*>(dst + base);
        int4 s = *reinterpret_cast<const int4*>(src + base);
        int p0 = atomicAdd(&g_cursor[d.x], 1);
        int p1 = atomicAdd(&g_cursor[d.y], 1);
        int p2 = atomicAdd(&g_cursor[d.z], 1);
        int p3 = atomicAdd(&g_cursor[d.w], 1);
        g_col[p0] = s.x;
        g_col[p1] = s.y;
        g_col[p2] = s.z;
        g_col[p3] = s.w;
    } else {
        for (int j = base; j < E; j++) {
            int p = atomicAdd(&g_cursor[dst[j]], 1);
            g_col[p] = src[j];
        }
    }
}

// ---------------- agg112: out = relu(Y_i + sum_j Y_j + b1), warp/node, float4 ----------------
__global__ __launch_bounds__(256) void agg112_kernel(const float* __restrict__ Y,
                                                     const float* __restrict__ b1,
                                                     float* __restrict__ out) {
    int node = blockIdx.x * 8 + (threadIdx.x >> 5);
    if (node >= NN) return;
    int lane = threadIdx.x & 31;
    int beg = __ldg(&g_rowptr[node]);
    int end = __ldg(&g_rowptr[node + 1]);
    bool act = lane < 28;
    size_t foff = (size_t)(lane << 2);

    float4 acc  = make_float4(0.f, 0.f, 0.f, 0.f);
    float4 acc1 = acc, acc2 = acc, acc3 = acc;
    if (act) acc = *reinterpret_cast<const float4*>(Y + (size_t)node * FI + foff);

    int e = beg;
    for (; e + 4 <= end; e += 4) {
        int s0 = __ldg(&g_col[e + 0]);
        int s1 = __ldg(&g_col[e + 1]);
        int s2 = __ldg(&g_col[e + 2]);
        int s3 = __ldg(&g_col[e + 3]);
        if (act) {
            float4 v0 = *reinterpret_cast<const float4*>(Y + (size_t)s0 * FI + foff);
            float4 v1 = *reinterpret_cast<const float4*>(Y + (size_t)s1 * FI + foff);
            float4 v2 = *reinterpret_cast<const float4*>(Y + (size_t)s2 * FI + foff);
            float4 v3 = *reinterpret_cast<const float4*>(Y + (size_t)s3 * FI + foff);
            acc.x += v0.x; acc.y += v0.y; acc.z += v0.z; acc.w += v0.w;
            acc1.x += v1.x; acc1.y += v1.y; acc1.z += v1.z; acc1.w += v1.w;
            acc2.x += v2.x; acc2.y += v2.y; acc2.z += v2.z; acc2.w += v2.w;
            acc3.x += v3.x; acc3.y += v3.y; acc3.z += v3.z; acc3.w += v3.w;
        }
    }
    for (; e < end; e++) {
        int s = __ldg(&g_col[e]);
        if (act) {
            float4 v = *reinterpret_cast<const float4*>(Y + (size_t)s * FI + foff);
            acc.x += v.x; acc.y += v.y; acc.z += v.z; acc.w += v.w;
        }
    }
    if (!act) return;
    float4 b = *reinterpret_cast<const float4*>(b1 + foff);
    float4 r;
    r.x = fmaxf((acc.x + acc1.x) + (acc2.x + acc3.x) + b.x, 0.f);
    r.y = fmaxf((acc.y + acc1.y) + (acc2.y + acc3.y) + b.y, 0.f);
    r.z = fmaxf((acc.z + acc1.z) + (acc2.z + acc3.z) + b.z, 0.f);
    r.w = fmaxf((acc.w + acc1.w) + (acc2.w + acc3.w) + b.w, 0.f);
    *reinterpret_cast<float4*>(out + (size_t)node * FI + foff) = r;
}

// ---------------- agg32: Z = relu(Y2_i + sum_j Y2_j + (1+deg)*K2C + b21) ----------------
__global__ __launch_bounds__(256) void agg32_kernel(const float* __restrict__ Y2,
                                                    const float* __restrict__ b21,
                                                    float* __restrict__ Z) {
    int node = blockIdx.x * 8 + (threadIdx.x >> 5);
    if (node >= NN) return;
    int lane = threadIdx.x & 31;
    int beg = __ldg(&g_rowptr[node]);
    int end = __ldg(&g_rowptr[node + 1]);

    float acc = Y2[(size_t)node * DM + lane];
    float a1v = 0.f, a2v = 0.f, a3v = 0.f;
    int e = beg;
    for (; e + 4 <= end; e += 4) {
        int s0 = __ldg(&g_col[e + 0]);
        int s1 = __ldg(&g_col[e + 1]);
        int s2 = __ldg(&g_col[e + 2]);
        int s3 = __ldg(&g_col[e + 3]);
        acc += Y2[(size_t)s0 * DM + lane];
        a1v += Y2[(size_t)s1 * DM + lane];
        a2v += Y2[(size_t)s2 * DM + lane];
        a3v += Y2[(size_t)s3 * DM + lane];
    }
    for (; e < end; e++) acc += Y2[(size_t)__ldg(&g_col[e]) * DM + lane];
    float dp1 = (float)(1 + end - beg);
    float z = (acc + a1v) + (a2v + a3v) + dp1 * g_k2c[lane] + __ldg(&b21[lane]);
    Z[(size_t)node * DM + lane] = fmaxf(z, 0.f);
}

// ---------------- 112x112 GEMM: 128-row tiles, 8 rows x 7 cols / thread, f32x2 ----------------
template<int BIAS_RELU, int STATS>
__global__ __launch_bounds__(256) void gemm112_kernel(const float* __restrict__ A,
                                                      const float* __restrict__ W,
                                                      const float* __restrict__ bias,
                                                      float* __restrict__ C, int M) {
    __shared__ __align__(16) float  As[16][132];
    __shared__ __align__(16) float2 Wd[16][112];
    const int tid = threadIdx.x;
    const int tr = tid >> 4;
    const int tc = tid & 15;
    const int row0 = blockIdx.x * 128;

    u64 acc01[7], acc23[7], acc45[7], acc67[7];
#pragma unroll
    for (int j = 0; j < 7; j++) { acc01[j] = 0ull; acc23[j] = 0ull; acc45[j] = 0ull; acc67[j] = 0ull; }

    for (int kc = 0; kc < 112; kc += 16) {
#pragma unroll
        for (int i = 0; i < 2; i++) {
            int idx = tid + i * 256;
            int r = idx >> 2;
            int kq = (idx & 3) << 2;
            float4 v = make_float4(0.f, 0.f, 0.f, 0.f);
            if (row0 + r < M)
                v = *reinterpret_cast<const float4*>(A + (size_t)(row0 + r) * 112 + kc + kq);
            As[kq + 0][r] = v.x;
            As[kq + 1][r] = v.y;
            As[kq + 2][r] = v.z;
            As[kq + 3][r] = v.w;
        }
#pragma unroll
        for (int i = 0; i < 7; i++) {
            int idx = tid + i * 256;
            int c = idx % 112, kk = idx / 112;
            float w = W[(size_t)(kc + kk) * 112 + c];
            Wd[kk][c] = make_float2(w, w);
        }
        __syncthreads();
#pragma unroll
        for (int kk = 0; kk < 16; kk++) {
            float4 alo = *reinterpret_cast<const float4*>(&As[kk][tr * 8]);
            float4 ahi = *reinterpret_cast<const float4*>(&As[kk][tr * 8 + 4]);
            u64 a01, a23, a45, a67;
            asm("mov.b64 %0, {%1, %2};" : "=l"(a01) : "f"(alo.x), "f"(alo.y));
            asm("mov.b64 %0, {%1, %2};" : "=l"(a23) : "f"(alo.z), "f"(alo.w));
            asm("mov.b64 %0, {%1, %2};" : "=l"(a45) : "f"(ahi.x), "f"(ahi.y));
            asm("mov.b64 %0, {%1, %2};" : "=l"(a67) : "f"(ahi.z), "f"(ahi.w));
#pragma unroll
            for (int j = 0; j < 7; j++) {
                u64 wp = *reinterpret_cast<const u64*>(&Wd[kk][tc * 7 + j]);
                asm("fma.rn.f32x2 %0, %1, %2, %0;" : "+l"(acc01[j]) : "l"(a01), "l"(wp));
                asm("fma.rn.f32x2 %0, %1, %2, %0;" : "+l"(acc23[j]) : "l"(a23), "l"(wp));
                asm("fma.rn.f32x2 %0, %1, %2, %0;" : "+l"(acc45[j]) : "l"(a45), "l"(wp));
                asm("fma.rn.f32x2 %0, %1, %2, %0;" : "+l"(acc67[j]) : "l"(a67), "l"(wp));
            }
        }
        __syncthreads();
    }

    const int r0 = row0 + tr * 8;
    float s[7], q[7];
#pragma unroll
    for (int j = 0; j < 7; j++) {
        int c = tc * 7 + j;
        float b = BIAS_RELU ? __ldg(&bias[c]) : 0.f;
        float v[8];
        asm("mov.b64 {%0, %1}, %2;" : "=f"(v[0]), "=f"(v[1]) : "l"(acc01[j]));
        asm("mov.b64 {%0, %1}, %2;" : "=f"(v[2]), "=f"(v[3]) : "l"(acc23[j]));
        asm("mov.b64 {%0, %1}, %2;" : "=f"(v[4]), "=f"(v[5]) : "l"(acc45[j]));
        asm("mov.b64 {%0, %1}, %2;" : "=f"(v[6]), "=f"(v[7]) : "l"(acc67[j]));
        float ss = 0.f, qq = 0.f;
#pragma unroll
        for (int i = 0; i < 8; i++) {
            float o = BIAS_RELU ? fmaxf(v[i] + b, 0.f) : v[i];
            if (r0 + i < M) {
                C[(size_t)(r0 + i) * 112 + c] = o;
                ss += o;
                qq += o * o;
            }
        }
        s[j] = ss; q[j] = qq;
    }

    if (STATS) {
        __syncthreads();
#pragma unroll
        for (int j = 0; j < 7; j++)
            Wd[tr][tc * 7 + j] = make_float2(s[j], q[j]);
        __syncthreads();
        if (tid < 112) {
            float S = 0.f, Q = 0.f;
#pragma unroll
            for (int t = 0; t < 16; t++) {
                float2 p = Wd[t][tid];
                S += p.x; Q += p.y;
            }
            atomicAdd(&g_sum1[tid], (double)S);
            atomicAdd(&g_sq1[tid],  (double)Q);
        }
    }
}

// ---------------- gemmY2: Y2 = (a1*H) @ W21, BN1 params computed in-kernel ----------------
#define SWZ(k, r) (((((r) >> 2) ^ ((k) & 15)) << 2) | ((r) & 3))
__global__ __launch_bounds__(256) void gemmY2_kernel(const float* __restrict__ H,
                                                     const float* __restrict__ W21,
                                                     const float* __restrict__ bn1g,
                                                     const float* __restrict__ bn1b,
                                                     float* __restrict__ Y2, int M) {
    __shared__ __align__(16) float Bs[112 * 64];
    __shared__ __align__(16) float W1s[112][32];
    __shared__ float a1s[FI], c1s[FI];
    const int tid = threadIdx.x;
    const int tr = tid >> 4;
    const int tc = tid & 15;
    const int row0 = blockIdx.x * 64;

    // BN1 affine params (every block computes its own copy)
    if (tid < FI) {
        double m = g_sum1[tid] / (double)NN;
        double var = g_sq1[tid] / (double)NN - m * m;
        float rs = rsqrtf((float)var + BN_EPS);
        float af = __ldg(&bn1g[tid]) * rs;
        a1s[tid] = af;
        c1s[tid] = __ldg(&bn1b[tid]) - (float)m * af;
    }
    for (int idx = tid; idx < 112 * 32; idx += 256) W1s[idx >> 5][idx & 31] = W21[idx];
    __syncthreads();

    for (int idx = tid; idx < 64 * 112; idx += 256) {
        int k = idx % 112, r = idx / 112;
        float v = (row0 + r < M) ? H[(size_t)(row0 + r) * 112 + k] * a1s[k] : 0.f;
        Bs[k * 64 + SWZ(k, r)] = v;
    }
    // K2C = c1^T @ W21 (redundant identical writes across blocks — deterministic)
    if (tid < DM) {
        float s = 0.f;
        for (int k = 0; k < FI; k++) s += c1s[k] * W1s[k][tid];
        g_k2c[tid] = s;
    }
    __syncthreads();

    u64 z01[2], z23[2];
#pragma unroll
    for (int j = 0; j < 2; j++) { z01[j] = 0ull; z23[j] = 0ull; }
    for (int k = 0; k < 112; k++) {
        int grp = (tr ^ (k & 15)) << 2;
        float4 av = *reinterpret_cast<const float4*>(&Bs[k * 64 + grp]);
        u64 a01, a23;
        asm("mov.b64 %0, {%1, %2};" : "=l"(a01) : "f"(av.x), "f"(av.y));
        asm("mov.b64 %0, {%1, %2};" : "=l"(a23) : "f"(av.z), "f"(av.w));
        float2 w = *reinterpret_cast<const float2*>(&W1s[k][tc * 2]);
        u64 w0, w1;
        asm("mov.b64 %0, {%1, %1};" : "=l"(w0) : "f"(w.x));
        asm("mov.b64 %0, {%1, %1};" : "=l"(w1) : "f"(w.y));
        asm("fma.rn.f32x2 %0, %1, %2, %0;" : "+l"(z01[0]) : "l"(a01), "l"(w0));
        asm("fma.rn.f32x2 %0, %1, %2, %0;" : "+l"(z23[0]) : "l"(a23), "l"(w0));
        asm("fma.rn.f32x2 %0, %1, %2, %0;" : "+l"(z01[1]) : "l"(a01), "l"(w1));
        asm("fma.rn.f32x2 %0, %1, %2, %0;" : "+l"(z23[1]) : "l"(a23), "l"(w1));
    }
    float v0, v1, v2, v3, u0, u1, u2, u3;
    asm("mov.b64 {%0, %1}, %2;" : "=f"(v0), "=f"(v1) : "l"(z01[0]));
    asm("mov.b64 {%0, %1}, %2;" : "=f"(v2), "=f"(v3) : "l"(z23[0]));
    asm("mov.b64 {%0, %1}, %2;" : "=f"(u0), "=f"(u1) : "l"(z01[1]));
    asm("mov.b64 {%0, %1}, %2;" : "=f"(u2), "=f"(u3) : "l"(z23[1]));
    float rr[4][2] = {{v0, u0}, {v1, u1}, {v2, u2}, {v3, u3}};
#pragma unroll
    for (int i = 0; i < 4; i++) {
        int r = row0 + tr * 4 + i;
        if (r < M)
            *reinterpret_cast<float2*>(Y2 + (size_t)r * DM + tc * 2) = make_float2(rr[i][0], rr[i][1]);
    }
}

// ---------------- gemm32: relu(Z @ W22 + b22), fused stats2 + pool + cnt ----------------
__global__ __launch_bounds__(256) void gemm32_kernel(const float* __restrict__ Z,
                                                     const float* __restrict__ W22,
                                                     const float* __restrict__ b22,
                                                     const int* __restrict__ batch, int M) {
    __shared__ __align__(16) float Zs[32 * 64];
    __shared__ __align__(16) float W2s[32][32];
    const int tid = threadIdx.x;
    const int tr = tid >> 4;
    const int tc = tid & 15;
    const int row0 = blockIdx.x * 64;

    for (int idx = tid; idx < 32 * 32; idx += 256) W2s[idx >> 5][idx & 31] = W22[idx];
    for (int idx = tid; idx < 64 * 32; idx += 256) {
        int k = idx % 32, r = idx / 32;
        float v = (row0 + r < M) ? Z[(size_t)(row0 + r) * 32 + k] : 0.f;
        Zs[k * 64 + SWZ(k, r)] = v;
    }
    __syncthreads();

    u64 h01[2], h23[2];
#pragma unroll
    for (int j = 0; j < 2; j++) { h01[j] = 0ull; h23[j] = 0ull; }
#pragma unroll
    for (int k = 0; k < 32; k++) {
        int grp = (tr ^ (k & 15)) << 2;
        float4 av = *reinterpret_cast<const float4*>(&Zs[k * 64 + grp]);
        u64 a01, a23;
        asm("mov.b64 %0, {%1, %2};" : "=l"(a01) : "f"(av.x), "f"(av.y));
        asm("mov.b64 %0, {%1, %2};" : "=l"(a23) : "f"(av.z), "f"(av.w));
        float2 w = *reinterpret_cast<const float2*>(&W2s[k][tc * 2]);
        u64 w0, w1;
        asm("mov.b64 %0, {%1, %1};" : "=l"(w0) : "f"(w.x));
        asm("mov.b64 %0, {%1, %1};" : "=l"(w1) : "f"(w.y));
        asm("fma.rn.f32x2 %0, %1, %2, %0;" : "+l"(h01[0]) : "l"(a01), "l"(w0));
        asm("fma.rn.f32x2 %0, %1, %2, %0;" : "+l"(h23[0]) : "l"(a23), "l"(w0));
        asm("fma.rn.f32x2 %0, %1, %2, %0;" : "+l"(h01[1]) : "l"(a01), "l"(w1));
        asm("fma.rn.f32x2 %0, %1, %2, %0;" : "+l"(h23[1]) : "l"(a23), "l"(w1));
    }

    float b0 = __ldg(&b22[tc * 2]);
    float b1 = __ldg(&b22[tc * 2 + 1]);
    float v0, v1, v2, v3, u0, u1, u2, u3;
    asm("mov.b64 {%0, %1}, %2;" : "=f"(v0), "=f"(v1) : "l"(h01[0]));
    asm("mov.b64 {%0, %1}, %2;" : "=f"(v2), "=f"(v3) : "l"(h23[0]));
    asm("mov.b64 {%0, %1}, %2;" : "=f"(u0), "=f"(u1) : "l"(h01[1]));
    asm("mov.b64 {%0, %1}, %2;" : "=f"(u2), "=f"(u3) : "l"(h23[1]));
    float rr[4][2] = {{v0, u0}, {v1, u1}, {v2, u2}, {v3, u3}};

    float s0 = 0.f, q0 = 0.f, s1 = 0.f, q1 = 0.f;
#pragma unroll
    for (int i = 0; i < 4; i++) {
        int r = row0 + tr * 4 + i;
        float o0 = fmaxf(rr[i][0] + b0, 0.f);
        float o1 = fmaxf(rr[i][1] + b1, 0.f);
        rr[i][0] = o0; rr[i][1] = o1;
        if (r < M) {
            s0 += o0; q0 += o0 * o0;
            s1 += o1; q1 += o1 * o1;
        }
    }

    __syncthreads();
    float2* part = reinterpret_cast<float2*>(Zs);
    part[tr * 32 + tc * 2]     = make_float2(s0, q0);
    part[tr * 32 + tc * 2 + 1] = make_float2(s1, q1);
    __syncthreads();
    if (tid < 32) {
        float S = 0.f, Q = 0.f;
#pragma unroll
        for (int t = 0; t < 16; t++) {
            float2 p = part[t * 32 + tid];
            S += p.x; Q += p.y;
        }
        atomicAdd(&g_sum2[tid], (double)S);
        atomicAdd(&g_sq2[tid],  (double)Q);
    }

#pragma unroll
    for (int i = 0; i < 4; i++) {
        int r = row0 + tr * 4 + i;
        if (r < M) {
            int b = __ldg(&batch[r]);
            atomicAdd(&g_pool[b * DM + tc * 2],     rr[i][0]);
            atomicAdd(&g_pool[b * DM + tc * 2 + 1], rr[i][1]);
            if (tc == 0) atomicAdd(&g_cnt[b], 1);
        }
    }
}

// ---------------- dense head (computes BN2 affine in-kernel) ----------------
__global__ void head_kernel(const float* __restrict__ bn2g, const float* __restrict__ bn2b,
                            const float* __restrict__ fcxd_w, const float* __restrict__ fcxd_b,
                            const float* __restrict__ fc1_w,  const float* __restrict__ fc1_b,
                            const float* __restrict__ fc2_w,  const float* __restrict__ fc2_b,
                            const float* __restrict__ fc3_w,  const float* __restrict__ fc3_b,
                            const float* __restrict__ fc4_w,  const float* __restrict__ fc4_b,
                            const float* __restrict__ fc5_w,  const float* __restrict__ fc5_b,
                            float* __restrict__ out) {
    __shared__ float p[DM], z1[64], z2[32], z3[16], z4[8], z5[2];
    int g = blockIdx.x, t = threadIdx.x;
    if (t < DM) {
        double m = g_sum2[t] / (double)NN;
        double var = g_sq2[t] / (double)NN - m * m;
        float rs = rsqrtf((float)var + BN_EPS);
        float af = __ldg(&bn2g[t]) * rs;
        float cf = __ldg(&bn2b[t]) - (float)m * af;
        float cnt = (float)g_cnt[g];
        p[t] = af * g_pool[g * DM + t] + cnt * cf;
    }
    __syncthreads();
    if (t < 64) {
        float s = fcxd_b[t];
        for (int k = 0; k < 32; k++) s += p[k] * fcxd_w[k * 64 + t];
        z1[t] = fmaxf(s, 0.0f);
    }
    __syncthreads();
    if (t < 32) {
        float s = fc1_b[t];
        for (int k = 0; k < 64; k++) s += z1[k] * fc1_w[k * 32 + t];
        z2[t] = s;
    }
    __syncthreads();
    if (t < 16) {
        float s = fc2_b[t];
        for (int k = 0; k < 32; k++) s += z2[k] * fc2_w[k * 16 + t];
        z3[t] = s;
    }
    __syncthreads();
    if (t < 8) {
        float s = fc3_b[t];
        for (int k = 0; k < 16; k++) s += z3[k] * fc3_w[k * 8 + t];
        z4[t] = s;
    }
    __syncthreads();
    if (t < 2) {
        float s = fc4_b[t];
        for (int k = 0; k < 8; k++) s += z4[k] * fc4_w[k * 2 + t];
        z5[t] = s;
    }
    __syncthreads();
    if (t == 0) out[g] = z5[0] * fc5_w[0] + z5[1] * fc5_w[1] + fc5_b[0];
}

// ---------------- launch ----------------
extern "C" void kernel_launch(void* const* d_in, const int* in_sizes, int n_in,
                              void* d_out, int out_size) {
    const float* x      = (const float*)d_in[0];
    const int*   src    = (const int*)d_in[1];
    const int*   dst    = (const int*)d_in[2];
    const int*   batch  = (const int*)d_in[3];
    const float* g1_w1  = (const float*)d_in[4];
    const float* g1_b1  = (const float*)d_in[5];
    const float* g1_w2  = (const float*)d_in[6];
    const float* g1_b2  = (const float*)d_in[7];
    const float* bn1_g  = (const float*)d_in[8];
    const float* bn1_b  = (const float*)d_in[9];
    const float* g2_w1  = (const float*)d_in[10];
    const float* g2_b1  = (const float*)d_in[11];
    const float* g2_w2  = (const float*)d_in[12];
    const float* g2_b2  = (const float*)d_in[13];
    const float* bn2_g  = (const float*)d_in[14];
    const float* bn2_b  = (const float*)d_in[15];
    const float* fcxd_w = (const float*)d_in[16];
    const float* fcxd_b = (const float*)d_in[17];
    const float* fc1_w  = (const float*)d_in[18];
    const float* fc1_b  = (const float*)d_in[19];
    const float* fc2_w  = (const float*)d_in[20];
    const float* fc2_b  = (const float*)d_in[21];
    const float* fc3_w  = (const float*)d_in[22];
    const float* fc3_b  = (const float*)d_in[23];
    const float* fc4_w  = (const float*)d_in[24];
    const float* fc4_b  = (const float*)d_in[25];
    const float* fc5_w  = (const float*)d_in[26];
    const float* fc5_b  = (const float*)d_in[27];
    float* out = (float*)d_out;

    const int E = in_sizes[1];
    const int M = NN;

    float *Y1, *T, *H, *Y2, *Z;
    cudaGetSymbolAddress((void**)&Y1, g_A);
    cudaGetSymbolAddress((void**)&T,  g_T);
    cudaGetSymbolAddress((void**)&H,  g_H);
    cudaGetSymbolAddress((void**)&Y2, g_Y2);
    cudaGetSymbolAddress((void**)&Z,  g_Z);

    // side stream + events (created once, before any capture)
    static cudaStream_t s_side = nullptr;
    static cudaEvent_t ev_fork = nullptr, ev_join = nullptr;
    if (s_side == nullptr) {
        cudaStreamCreateWithFlags(&s_side, cudaStreamNonBlocking);
        cudaEventCreateWithFlags(&ev_fork, cudaEventDisableTiming);
        cudaEventCreateWithFlags(&ev_join, cudaEventDisableTiming);
    }

    // fork: CSR build runs on side stream, overlapped with first GEMM
    cudaEventRecord(ev_fork, 0);
    cudaStreamWaitEvent(s_side, ev_fork, 0);
    zero_kernel<<<(NN + 255) / 256, 256, 0, s_side>>>();
    hist_kernel<<<((E + 3) / 4 + 255) / 256, 256, 0, s_side>>>(dst, E);
    scan_kernel<<<1, 1024, 0, s_side>>>();
    fill_kernel<<<((E + 3) / 4 + 255) / 256, 256, 0, s_side>>>(src, dst, E);
    cudaEventRecord(ev_join, s_side);

    // main stream: Y1 = x @ W11 (independent of CSR)
    gemm112_kernel<0, 0><<<(M + 127) / 128, 256>>>(x, g1_w1, nullptr, Y1, M);

    // join
    cudaStreamWaitEvent(0, ev_join, 0);

    // ---- GIN layer 1 ----
    agg112_kernel<<<(NN + 7) / 8, 256>>>(Y1, g1_b1, T);                        // T = relu(Y1+agg+b1)
    gemm112_kernel<1, 1><<<(M + 127) / 128, 256>>>(T, g1_w2, g1_b2, H, M);     // H = relu(T@W12+b2) + stats1

    // ---- GIN layer 2 (32-wide aggregation; BN1 folded) ----
    gemmY2_kernel<<<(M + 63) / 64, 256>>>(H, g2_w1, bn1_g, bn1_b, Y2, M);      // Y2 = (a1*H)@W21, k2c
    agg32_kernel<<<(NN + 7) / 8, 256>>>(Y2, g2_b1, Z);                         // Z = relu(Y2+agg+(1+deg)k2c+b21)
    gemm32_kernel<<<(M + 63) / 64, 256>>>(Z, g2_w2, g2_b2, batch, M);          // relu GEMM + stats2 + pool + cnt

    // ---- head (BN2 affine in-kernel) ----
    head_kernel<<<NG, 64>>>(bn2_g, bn2_b, fcxd_w, fcxd_b, fc1_w, fc1_b, fc2_w, fc2_b,
                            fc3_w, fc3_b, fc4_w, fc4_b, fc5_w, fc5_b, out);
}